// round 5
// baseline (speedup 1.0000x reference)
#include <cuda_runtime.h>
#include <math.h>
#include <stdint.h>

// Problem constants
constexpr int B  = 4;
constexpr int T  = 1024;
constexpr int E  = 1024;
constexpr int H  = 16;
constexpr int BT = B * T;              // 4096 rows
constexpr float EPS = 1e-5f;
constexpr float SCALE = 0.03125f;      // E^-0.5 = 1/32

// ---------------- scratch (no cudaMalloc allowed) ----------------
__device__ float g_ln[3][BT * E];      // tf32-rounded LN outputs
__device__ float g_w[4][E * E];        // tf32-rounded weights (Wq,Wk,Wv,Wp)
__device__ float g_proj[3][BT * E];    // tf32-rounded projected q/k/v [bt][h*64+d]
__device__ float g_att[BT * E];        // tf32-rounded attention out [bt][e]

// ---------------- tf32 mma helpers ----------------
__device__ __forceinline__ uint32_t f2tf(float x) {
    uint32_t u; asm("cvt.rna.tf32.f32 %0, %1;" : "=r"(u) : "f"(x)); return u;
}
__device__ __forceinline__ float rtf(float x) { return __uint_as_float(f2tf(x)); }
__device__ __forceinline__ void mma8(float* c, const uint32_t* a, const uint32_t* b) {
    asm volatile(
        "mma.sync.aligned.m16n8k8.row.col.f32.tf32.tf32.f32 "
        "{%0,%1,%2,%3}, {%4,%5,%6,%7}, {%8,%9}, {%0,%1,%2,%3};"
        : "+f"(c[0]), "+f"(c[1]), "+f"(c[2]), "+f"(c[3])
        : "r"(a[0]), "r"(a[1]), "r"(a[2]), "r"(a[3]), "r"(b[0]), "r"(b[1]));
}
__device__ __forceinline__ void cpasync16(void* s, const void* g) {
    uint32_t sa = (uint32_t)__cvta_generic_to_shared(s);
    asm volatile("cp.async.ca.shared.global [%0], [%1], 16;" :: "r"(sa), "l"(g));
}
#define CP_COMMIT() asm volatile("cp.async.commit_group;")
#define CP_WAIT0()  asm volatile("cp.async.wait_group 0;")

// ---------------- weight pre-round: 4 matrices -> g_w ----------------
__global__ void __launch_bounds__(256) round_w(
    const float* __restrict__ wq, const float* __restrict__ wk,
    const float* __restrict__ wv, const float* __restrict__ wp)
{
    int which = blockIdx.y;
    const float* src = (which == 0) ? wq : (which == 1) ? wk : (which == 2) ? wv : wp;
    float* dst = g_w[which];
    int i = (blockIdx.x * 256 + threadIdx.x) * 4;
    float4 v = *(const float4*)(src + i);
    v.x = rtf(v.x); v.y = rtf(v.y); v.z = rtf(v.z); v.w = rtf(v.w);
    *(float4*)(dst + i) = v;
}

// ---------------- block reduction helper ----------------
__device__ __forceinline__ float block_sum_256(float v) {
    __shared__ float sh[8];
    int tid = threadIdx.x;
    #pragma unroll
    for (int o = 16; o; o >>= 1) v += __shfl_xor_sync(0xffffffffu, v, o);
    if ((tid & 31) == 0) sh[tid >> 5] = v;
    __syncthreads();
    float r = (tid < 8) ? sh[tid] : 0.f;
    if (tid < 32) {
        #pragma unroll
        for (int o = 4; o; o >>= 1) r += __shfl_xor_sync(0xffffffffu, r, o);
        if (tid == 0) sh[0] = r;
    }
    __syncthreads();
    r = sh[0];
    __syncthreads();
    return r;
}

// ---------------- LayerNorm: one block per (row, stream) ----------------
__global__ void __launch_bounds__(256) ln_kernel(
    const float* __restrict__ q, const float* __restrict__ k,
    const float* __restrict__ v, const float* __restrict__ gamma,
    const float* __restrict__ beta)
{
    int stream = blockIdx.y;
    int row    = blockIdx.x;
    const float* x = (stream == 0) ? q : (stream == 1) ? k : v;
    float* y = g_ln[stream];
    x += (size_t)row * E;
    y += (size_t)row * E;
    int tid = threadIdx.x;

    float vals[4];
    float s = 0.f;
    #pragma unroll
    for (int i = 0; i < 4; i++) { vals[i] = x[tid + 256 * i]; s += vals[i]; }
    float mu = block_sum_256(s) * (1.f / E);

    float vs = 0.f;
    #pragma unroll
    for (int i = 0; i < 4; i++) { float d = vals[i] - mu; vs += d * d; }
    float var = block_sum_256(vs) * (1.f / E);
    float inv = rsqrtf(var + EPS);

    #pragma unroll
    for (int i = 0; i < 4; i++) {
        int e = tid + 256 * i;
        y[e] = rtf((vals[i] - mu) * inv * gamma[e] + beta[e]);
    }
}

// ---------------- TF32 tensor-core GEMM 128x128x32, 1-sync cp.async pipeline ----------------
constexpr int BM = 128, BN = 128, BK = 32;
constexpr int ASTRIDE = 36;
constexpr int BSTRIDE = 136;
constexpr int ABUF = BM * ASTRIDE;
constexpr int BBUF = BK * BSTRIDE;
constexpr int GEMM_SMEM = (2 * ABUF + 2 * BBUF) * (int)sizeof(float);  // 71680

// OUT=false: A=g_ln[z], C=g_proj[z] (tf32-rounded). OUT=true: A=g_att, C=Cext+bias.
template<bool OUT>
__device__ __forceinline__ void gemm_body(
    const float* __restrict__ A, const float* __restrict__ W,
    const float* __restrict__ bias, float* __restrict__ C)
{
    extern __shared__ float sm[];
    float* As = sm;              // [2][ABUF]
    float* Bs = sm + 2 * ABUF;   // [2][BBUF]

    int m0 = blockIdx.y * BM, n0 = blockIdx.x * BN;
    int tid = threadIdx.x, lane = tid & 31, wid = tid >> 5;
    int g = lane >> 2, t = lane & 3;
    int wm = (wid & 1) * 64, wn = (wid >> 1) * 32;

    auto load_tiles = [&](int buf, int k0) {
        #pragma unroll
        for (int i = 0; i < 4; i++) {
            int idx = tid + i * 256; int r = idx >> 3, c4 = idx & 7;
            cpasync16(&As[buf * ABUF + r * ASTRIDE + c4 * 4],
                      A + (size_t)(m0 + r) * E + k0 + c4 * 4);
        }
        #pragma unroll
        for (int i = 0; i < 4; i++) {
            int idx = tid + i * 256; int r = idx >> 5, c4 = idx & 31;
            cpasync16(&Bs[buf * BBUF + r * BSTRIDE + c4 * 4],
                      W + (size_t)(k0 + r) * E + n0 + c4 * 4);
        }
        CP_COMMIT();
    };

    float acc[4][4][4] = {};
    load_tiles(0, 0);

    for (int kt = 0; kt < E / BK; kt++) {
        CP_WAIT0();              // tile kt arrived (kt+1 not yet committed)
        __syncthreads();         // visibility + all warps done reading buf (kt-1)&1
        if (kt + 1 < E / BK) load_tiles((kt + 1) & 1, (kt + 1) * BK);
        const float* a_ = &As[(kt & 1) * ABUF];
        const float* b_ = &Bs[(kt & 1) * BBUF];
        #pragma unroll
        for (int ks = 0; ks < 4; ks++) {
            int k0 = ks * 8;
            uint32_t af[4][4], bf[4][2];
            #pragma unroll
            for (int mt = 0; mt < 4; mt++) {
                int mr = wm + mt * 16;
                af[mt][0] = __float_as_uint(a_[(mr + g)     * ASTRIDE + k0 + t]);
                af[mt][1] = __float_as_uint(a_[(mr + g + 8) * ASTRIDE + k0 + t]);
                af[mt][2] = __float_as_uint(a_[(mr + g)     * ASTRIDE + k0 + t + 4]);
                af[mt][3] = __float_as_uint(a_[(mr + g + 8) * ASTRIDE + k0 + t + 4]);
            }
            #pragma unroll
            for (int nt = 0; nt < 4; nt++) {
                int nc = wn + nt * 8 + g;
                bf[nt][0] = __float_as_uint(b_[(k0 + t)     * BSTRIDE + nc]);
                bf[nt][1] = __float_as_uint(b_[(k0 + t + 4) * BSTRIDE + nc]);
            }
            #pragma unroll
            for (int mt = 0; mt < 4; mt++)
                #pragma unroll
                for (int nt = 0; nt < 4; nt++)
                    mma8(acc[mt][nt], af[mt], bf[nt]);
        }
    }

    #pragma unroll
    for (int mt = 0; mt < 4; mt++) {
        int r0 = m0 + wm + mt * 16 + g;
        #pragma unroll
        for (int nt = 0; nt < 4; nt++) {
            int c0 = n0 + wn + nt * 8 + 2 * t;
            float2 v;
            if (OUT) {
                float b0 = bias[c0], b1 = bias[c0 + 1];
                v.x = acc[mt][nt][0] + b0; v.y = acc[mt][nt][1] + b1;
                *(float2*)&C[(size_t)r0 * E + c0] = v;
                v.x = acc[mt][nt][2] + b0; v.y = acc[mt][nt][3] + b1;
                *(float2*)&C[(size_t)(r0 + 8) * E + c0] = v;
            } else {
                v.x = rtf(acc[mt][nt][0]); v.y = rtf(acc[mt][nt][1]);
                *(float2*)&C[(size_t)r0 * E + c0] = v;
                v.x = rtf(acc[mt][nt][2]); v.y = rtf(acc[mt][nt][3]);
                *(float2*)&C[(size_t)(r0 + 8) * E + c0] = v;
            }
        }
    }
}

__global__ void __launch_bounds__(256, 2) gemm_qkv() {
    int z = blockIdx.z;
    gemm_body<false>(g_ln[z], g_w[z], nullptr, g_proj[z]);
}
__global__ void __launch_bounds__(256, 2) gemm_out(
    const float* __restrict__ bias, float* __restrict__ Cext) {
    gemm_body<true>(g_att, g_w[3], bias, Cext);
}

// ---------------- tensor-core flash attention, cp.async double-buffered KV ----------------
constexpr int LDS_ = 68;
constexpr int KVT = 64 * LDS_;                         // one K or V tile (floats)
constexpr int ATT_SMEM = 6 * KVT * (int)sizeof(float); // Q + 2K + 2V + P = 104448

__global__ void __launch_bounds__(128) attn_tc() {
    extern __shared__ float sm[];
    float* Qs = sm;                 // [64][68]
    float* Ks = Qs + KVT;           // [2][64][68]
    float* Vs = Ks + 2 * KVT;       // [2][64][68]
    float* Ps = Vs + 2 * KVT;       // [64][68]

    int qt = blockIdx.x, h = blockIdx.y, b = blockIdx.z;
    const float* Q = g_proj[0] + ((size_t)b * T + qt * 64) * E + h * 64;
    const float* K = g_proj[1] + (size_t)b * T * E + h * 64;
    const float* V = g_proj[2] + (size_t)b * T * E + h * 64;

    int tid = threadIdx.x, lane = tid & 31, wid = tid >> 5;
    int g = lane >> 2, t = lane & 3;

    auto loadKV = [&](int buf, int kt) {
        const float* Kg = K + (size_t)(kt * 64) * E;
        const float* Vg = V + (size_t)(kt * 64) * E;
        float* Kd = Ks + buf * KVT;
        float* Vd = Vs + buf * KVT;
        #pragma unroll
        for (int i = 0; i < 8; i++) {
            int idx = tid + i * 128; int r = idx >> 4, c4 = idx & 15;
            cpasync16(&Kd[r * LDS_ + c4 * 4], Kg + (size_t)r * E + c4 * 4);
            cpasync16(&Vd[r * LDS_ + c4 * 4], Vg + (size_t)r * E + c4 * 4);
        }
        CP_COMMIT();
    };

    // load Q tile 64x64 (row stride E); values already tf32-rounded
    #pragma unroll
    for (int i = 0; i < 8; i++) {
        int idx = tid + i * 128; int r = idx >> 4, c4 = idx & 15;
        *(float4*)&Qs[r * LDS_ + c4 * 4] = *(const float4*)(Q + (size_t)r * E + c4 * 4);
    }
    loadKV(0, 0);
    __syncthreads();

    // Q fragments: multiply by 2^-5 (exact -> still valid tf32 bits)
    uint32_t qf[8][4];
    {
        int mr = wid * 16;
        #pragma unroll
        for (int ks = 0; ks < 8; ks++) {
            int k0 = ks * 8;
            qf[ks][0] = __float_as_uint(Qs[(mr + g)     * LDS_ + k0 + t]     * SCALE);
            qf[ks][1] = __float_as_uint(Qs[(mr + g + 8) * LDS_ + k0 + t]     * SCALE);
            qf[ks][2] = __float_as_uint(Qs[(mr + g)     * LDS_ + k0 + t + 4] * SCALE);
            qf[ks][3] = __float_as_uint(Qs[(mr + g + 8) * LDS_ + k0 + t + 4] * SCALE);
        }
    }

    float o[8][4] = {};
    float m0 = -1e30f, m1 = -1e30f, l0 = 0.f, l1 = 0.f;
    int row0 = qt * 64 + wid * 16 + g;
    int pr = wid * 16 + g;

    for (int kt = 0; kt <= qt; kt++) {
        CP_WAIT0();              // KV tile kt arrived
        __syncthreads();         // visibility + all warps done with buf (kt-1)&1
        if (kt + 1 <= qt) loadKV((kt + 1) & 1, kt + 1);
        const float* Kt = Ks + (kt & 1) * KVT;
        const float* Vt = Vs + (kt & 1) * KVT;

        // S = Q @ K^T  (16x64 per warp)
        float s[8][4] = {};
        #pragma unroll
        for (int ks = 0; ks < 8; ks++) {
            int k0 = ks * 8;
            #pragma unroll
            for (int nt = 0; nt < 8; nt++) {
                uint32_t bf[2];
                bf[0] = __float_as_uint(Kt[(nt * 8 + g) * LDS_ + k0 + t]);
                bf[1] = __float_as_uint(Kt[(nt * 8 + g) * LDS_ + k0 + t + 4]);
                mma8(s[nt], qf[ks], bf);
            }
        }

        if (kt == qt) {
            #pragma unroll
            for (int nt = 0; nt < 8; nt++) {
                int c = kt * 64 + nt * 8 + 2 * t;
                if (c     > row0)     s[nt][0] = -1e30f;
                if (c + 1 > row0)     s[nt][1] = -1e30f;
                if (c     > row0 + 8) s[nt][2] = -1e30f;
                if (c + 1 > row0 + 8) s[nt][3] = -1e30f;
            }
        }

        float mx0 = -1e30f, mx1 = -1e30f;
        #pragma unroll
        for (int nt = 0; nt < 8; nt++) {
            mx0 = fmaxf(mx0, fmaxf(s[nt][0], s[nt][1]));
            mx1 = fmaxf(mx1, fmaxf(s[nt][2], s[nt][3]));
        }
        mx0 = fmaxf(mx0, __shfl_xor_sync(0xffffffffu, mx0, 1));
        mx0 = fmaxf(mx0, __shfl_xor_sync(0xffffffffu, mx0, 2));
        mx1 = fmaxf(mx1, __shfl_xor_sync(0xffffffffu, mx1, 1));
        mx1 = fmaxf(mx1, __shfl_xor_sync(0xffffffffu, mx1, 2));
        float mn0 = fmaxf(m0, mx0), mn1 = fmaxf(m1, mx1);
        float c0 = __expf(m0 - mn0), c1 = __expf(m1 - mn1);

        float ps0 = 0.f, ps1 = 0.f;
        #pragma unroll
        for (int nt = 0; nt < 8; nt++) {
            float p0 = __expf(s[nt][0] - mn0), p1 = __expf(s[nt][1] - mn0);
            float p2 = __expf(s[nt][2] - mn1), p3 = __expf(s[nt][3] - mn1);
            ps0 += p0 + p1; ps1 += p2 + p3;
            float2 w0 = {rtf(p0), rtf(p1)}, w1 = {rtf(p2), rtf(p3)};
            *(float2*)&Ps[(size_t)pr * LDS_ + nt * 8 + 2 * t] = w0;
            *(float2*)&Ps[(size_t)(pr + 8) * LDS_ + nt * 8 + 2 * t] = w1;
        }
        ps0 += __shfl_xor_sync(0xffffffffu, ps0, 1);
        ps0 += __shfl_xor_sync(0xffffffffu, ps0, 2);
        ps1 += __shfl_xor_sync(0xffffffffu, ps1, 1);
        ps1 += __shfl_xor_sync(0xffffffffu, ps1, 2);
        l0 = l0 * c0 + ps0; l1 = l1 * c1 + ps1;
        m0 = mn0; m1 = mn1;

        #pragma unroll
        for (int nt = 0; nt < 8; nt++) {
            o[nt][0] *= c0; o[nt][1] *= c0;
            o[nt][2] *= c1; o[nt][3] *= c1;
        }
        __syncwarp();

        // O += P @ V
        #pragma unroll
        for (int ks = 0; ks < 8; ks++) {
            int k0 = ks * 8;
            uint32_t af[4];
            af[0] = __float_as_uint(Ps[(size_t)pr       * LDS_ + k0 + t]);
            af[1] = __float_as_uint(Ps[(size_t)(pr + 8) * LDS_ + k0 + t]);
            af[2] = __float_as_uint(Ps[(size_t)pr       * LDS_ + k0 + t + 4]);
            af[3] = __float_as_uint(Ps[(size_t)(pr + 8) * LDS_ + k0 + t + 4]);
            #pragma unroll
            for (int nt = 0; nt < 8; nt++) {
                uint32_t bf[2];
                bf[0] = __float_as_uint(Vt[(k0 + t)     * LDS_ + nt * 8 + g]);
                bf[1] = __float_as_uint(Vt[(k0 + t + 4) * LDS_ + nt * 8 + g]);
                mma8(o[nt], af, bf);
            }
        }
    }

    float i0 = 1.f / l0, i1 = 1.f / l1;
    float* O0 = g_att + ((size_t)b * T + row0) * E + h * 64;
    float* O1 = O0 + 8 * (size_t)E;
    #pragma unroll
    for (int nt = 0; nt < 8; nt++) {
        float2 w0 = {rtf(o[nt][0] * i0), rtf(o[nt][1] * i0)};
        float2 w1 = {rtf(o[nt][2] * i1), rtf(o[nt][3] * i1)};
        *(float2*)&O0[nt * 8 + 2 * t] = w0;
        *(float2*)&O1[nt * 8 + 2 * t] = w1;
    }
}

// ---------------- launch ----------------
extern "C" void kernel_launch(void* const* d_in, const int* in_sizes, int n_in,
                              void* d_out, int out_size)
{
    const float* v    = (const float*)d_in[0];
    const float* k    = (const float*)d_in[1];
    const float* q    = (const float*)d_in[2];
    const float* ln_g = (const float*)d_in[3];
    const float* ln_b = (const float*)d_in[4];
    const float* Wq   = (const float*)d_in[5];
    const float* Wk   = (const float*)d_in[6];
    const float* Wv   = (const float*)d_in[7];
    const float* Wp   = (const float*)d_in[8];
    const float* bp   = (const float*)d_in[9];
    float* out = (float*)d_out;

    cudaFuncSetAttribute(gemm_qkv, cudaFuncAttributeMaxDynamicSharedMemorySize, GEMM_SMEM);
    cudaFuncSetAttribute(gemm_out, cudaFuncAttributeMaxDynamicSharedMemorySize, GEMM_SMEM);
    cudaFuncSetAttribute(attn_tc,  cudaFuncAttributeMaxDynamicSharedMemorySize, ATT_SMEM);

    // 0) pre-round weights + LayerNorm
    round_w<<<dim3(E * E / 1024, 4), 256>>>(Wq, Wk, Wv, Wp);
    ln_kernel<<<dim3(BT, 3), 256>>>(q, k, v, ln_g, ln_b);

    // 1) QKV projections, fused into one launch (z = stream)
    gemm_qkv<<<dim3(E / BN, BT / BM, 3), 256, GEMM_SMEM>>>();

    // 2) causal flash attention (cp.async double-buffered KV)
    attn_tc<<<dim3(T / 64, H, B), 128, ATT_SMEM>>>();

    // 3) output projection + bias -> d_out
    gemm_out<<<dim3(E / BN, BT / BM), 256, GEMM_SMEM>>>(bp, out);
}

// round 6
// speedup vs baseline: 1.0506x; 1.0506x over previous
#include <cuda_runtime.h>
#include <math.h>
#include <stdint.h>

// Problem constants
constexpr int B  = 4;
constexpr int T  = 1024;
constexpr int E  = 1024;
constexpr int H  = 16;
constexpr int BT = B * T;              // 4096 rows
constexpr float EPS = 1e-5f;
constexpr float SCALE = 0.03125f;      // E^-0.5 = 1/32

// ---------------- scratch (no cudaMalloc allowed) ----------------
__device__ float g_ln[3][BT * E];      // tf32-rounded LN outputs
__device__ float g_w[4][E * E];        // tf32-rounded weights (Wq,Wk,Wv,Wp)
__device__ float g_proj[3][BT * E];    // tf32-rounded projected q/k/v [bt][h*64+d]
__device__ float g_att[BT * E];        // tf32-rounded attention out [bt][e]

// ---------------- tf32 mma helpers ----------------
__device__ __forceinline__ uint32_t f2tf(float x) {
    uint32_t u; asm("cvt.rna.tf32.f32 %0, %1;" : "=r"(u) : "f"(x)); return u;
}
__device__ __forceinline__ float rtf(float x) { return __uint_as_float(f2tf(x)); }
__device__ __forceinline__ void mma8(float* c, const uint32_t* a, const uint32_t* b) {
    asm volatile(
        "mma.sync.aligned.m16n8k8.row.col.f32.tf32.tf32.f32 "
        "{%0,%1,%2,%3}, {%4,%5,%6,%7}, {%8,%9}, {%0,%1,%2,%3};"
        : "+f"(c[0]), "+f"(c[1]), "+f"(c[2]), "+f"(c[3])
        : "r"(a[0]), "r"(a[1]), "r"(a[2]), "r"(a[3]), "r"(b[0]), "r"(b[1]));
}
__device__ __forceinline__ void cpasync16(void* s, const void* g) {
    uint32_t sa = (uint32_t)__cvta_generic_to_shared(s);
    asm volatile("cp.async.ca.shared.global [%0], [%1], 16;" :: "r"(sa), "l"(g));
}
#define CP_COMMIT() asm volatile("cp.async.commit_group;")
#define CP_WAIT0()  asm volatile("cp.async.wait_group 0;")
#define CP_WAIT1()  asm volatile("cp.async.wait_group 1;")

// ---------------- weight pre-round: 4 matrices -> g_w ----------------
__global__ void __launch_bounds__(256) round_w(
    const float* __restrict__ wq, const float* __restrict__ wk,
    const float* __restrict__ wv, const float* __restrict__ wp)
{
    int which = blockIdx.y;
    const float* src = (which == 0) ? wq : (which == 1) ? wk : (which == 2) ? wv : wp;
    float* dst = g_w[which];
    int i = (blockIdx.x * 256 + threadIdx.x) * 4;
    float4 v = *(const float4*)(src + i);
    v.x = rtf(v.x); v.y = rtf(v.y); v.z = rtf(v.z); v.w = rtf(v.w);
    *(float4*)(dst + i) = v;
}

// ---------------- block reduction helper ----------------
__device__ __forceinline__ float block_sum_256(float v) {
    __shared__ float sh[8];
    int tid = threadIdx.x;
    #pragma unroll
    for (int o = 16; o; o >>= 1) v += __shfl_xor_sync(0xffffffffu, v, o);
    if ((tid & 31) == 0) sh[tid >> 5] = v;
    __syncthreads();
    float r = (tid < 8) ? sh[tid] : 0.f;
    if (tid < 32) {
        #pragma unroll
        for (int o = 4; o; o >>= 1) r += __shfl_xor_sync(0xffffffffu, r, o);
        if (tid == 0) sh[0] = r;
    }
    __syncthreads();
    r = sh[0];
    __syncthreads();
    return r;
}

// ---------------- LayerNorm ----------------
__global__ void __launch_bounds__(256) ln_kernel(
    const float* __restrict__ q, const float* __restrict__ k,
    const float* __restrict__ v, const float* __restrict__ gamma,
    const float* __restrict__ beta)
{
    int stream = blockIdx.y;
    int row    = blockIdx.x;
    const float* x = (stream == 0) ? q : (stream == 1) ? k : v;
    float* y = g_ln[stream];
    x += (size_t)row * E;
    y += (size_t)row * E;
    int tid = threadIdx.x;

    float vals[4];
    float s = 0.f;
    #pragma unroll
    for (int i = 0; i < 4; i++) { vals[i] = x[tid + 256 * i]; s += vals[i]; }
    float mu = block_sum_256(s) * (1.f / E);

    float vs = 0.f;
    #pragma unroll
    for (int i = 0; i < 4; i++) { float d = vals[i] - mu; vs += d * d; }
    float var = block_sum_256(vs) * (1.f / E);
    float inv = rsqrtf(var + EPS);

    #pragma unroll
    for (int i = 0; i < 4; i++) {
        int e = tid + 256 * i;
        y[e] = rtf((vals[i] - mu) * inv * gamma[e] + beta[e]);
    }
}

// ---------------- TF32 tensor-core GEMM 128x128x32, 1-sync cp.async pipeline ----------------
constexpr int BM = 128, BN = 128, BK = 32;
constexpr int ASTRIDE = 36;
constexpr int BSTRIDE = 136;
constexpr int ABUF = BM * ASTRIDE;
constexpr int BBUF = BK * BSTRIDE;
constexpr int GEMM_SMEM = (2 * ABUF + 2 * BBUF) * (int)sizeof(float);  // 71680

template<bool OUT>
__device__ __forceinline__ void gemm_body(
    const float* __restrict__ A, const float* __restrict__ W,
    const float* __restrict__ bias, float* __restrict__ C)
{
    extern __shared__ float sm[];
    float* As = sm;              // [2][ABUF]
    float* Bs = sm + 2 * ABUF;   // [2][BBUF]

    int m0 = blockIdx.y * BM, n0 = blockIdx.x * BN;
    int tid = threadIdx.x, lane = tid & 31, wid = tid >> 5;
    int g = lane >> 2, t = lane & 3;
    int wm = (wid & 1) * 64, wn = (wid >> 1) * 32;

    auto load_tiles = [&](int buf, int k0) {
        #pragma unroll
        for (int i = 0; i < 4; i++) {
            int idx = tid + i * 256; int r = idx >> 3, c4 = idx & 7;
            cpasync16(&As[buf * ABUF + r * ASTRIDE + c4 * 4],
                      A + (size_t)(m0 + r) * E + k0 + c4 * 4);
        }
        #pragma unroll
        for (int i = 0; i < 4; i++) {
            int idx = tid + i * 256; int r = idx >> 5, c4 = idx & 31;
            cpasync16(&Bs[buf * BBUF + r * BSTRIDE + c4 * 4],
                      W + (size_t)(k0 + r) * E + n0 + c4 * 4);
        }
        CP_COMMIT();
    };

    float acc[4][4][4] = {};
    load_tiles(0, 0);

    for (int kt = 0; kt < E / BK; kt++) {
        CP_WAIT0();
        __syncthreads();
        if (kt + 1 < E / BK) load_tiles((kt + 1) & 1, (kt + 1) * BK);
        const float* a_ = &As[(kt & 1) * ABUF];
        const float* b_ = &Bs[(kt & 1) * BBUF];
        #pragma unroll
        for (int ks = 0; ks < 4; ks++) {
            int k0 = ks * 8;
            uint32_t af[4][4], bf[4][2];
            #pragma unroll
            for (int mt = 0; mt < 4; mt++) {
                int mr = wm + mt * 16;
                af[mt][0] = __float_as_uint(a_[(mr + g)     * ASTRIDE + k0 + t]);
                af[mt][1] = __float_as_uint(a_[(mr + g + 8) * ASTRIDE + k0 + t]);
                af[mt][2] = __float_as_uint(a_[(mr + g)     * ASTRIDE + k0 + t + 4]);
                af[mt][3] = __float_as_uint(a_[(mr + g + 8) * ASTRIDE + k0 + t + 4]);
            }
            #pragma unroll
            for (int nt = 0; nt < 4; nt++) {
                int nc = wn + nt * 8 + g;
                bf[nt][0] = __float_as_uint(b_[(k0 + t)     * BSTRIDE + nc]);
                bf[nt][1] = __float_as_uint(b_[(k0 + t + 4) * BSTRIDE + nc]);
            }
            #pragma unroll
            for (int mt = 0; mt < 4; mt++)
                #pragma unroll
                for (int nt = 0; nt < 4; nt++)
                    mma8(acc[mt][nt], af[mt], bf[nt]);
        }
    }

    #pragma unroll
    for (int mt = 0; mt < 4; mt++) {
        int r0 = m0 + wm + mt * 16 + g;
        #pragma unroll
        for (int nt = 0; nt < 4; nt++) {
            int c0 = n0 + wn + nt * 8 + 2 * t;
            float2 v;
            if (OUT) {
                float b0 = bias[c0], b1 = bias[c0 + 1];
                v.x = acc[mt][nt][0] + b0; v.y = acc[mt][nt][1] + b1;
                *(float2*)&C[(size_t)r0 * E + c0] = v;
                v.x = acc[mt][nt][2] + b0; v.y = acc[mt][nt][3] + b1;
                *(float2*)&C[(size_t)(r0 + 8) * E + c0] = v;
            } else {
                v.x = rtf(acc[mt][nt][0]); v.y = rtf(acc[mt][nt][1]);
                *(float2*)&C[(size_t)r0 * E + c0] = v;
                v.x = rtf(acc[mt][nt][2]); v.y = rtf(acc[mt][nt][3]);
                *(float2*)&C[(size_t)(r0 + 8) * E + c0] = v;
            }
        }
    }
}

__global__ void __launch_bounds__(256, 2) gemm_qkv() {
    int z = blockIdx.z;
    gemm_body<false>(g_ln[z], g_w[z], nullptr, g_proj[z]);
}
__global__ void __launch_bounds__(256, 2) gemm_out(
    const float* __restrict__ bias, float* __restrict__ Cext) {
    gemm_body<true>(g_att, g_w[3], bias, Cext);
}

// ---------------- flash attention: 3-tile smem (QP merged, rotating K/V) ----------------
constexpr int LDS_ = 68;
constexpr int KVT = 64 * LDS_;                         // one 64x64 tile (floats)
constexpr int ATT_SMEM = 3 * KVT * (int)sizeof(float); // QP + K + V = 52224

__global__ void __launch_bounds__(128) attn_tc() {
    extern __shared__ float sm[];
    float* QP = sm;             // Q at start, then P (rows are warp-exclusive)
    float* Kb = sm + KVT;
    float* Vb = sm + 2 * KVT;

    // descending q-tile size order: big blocks dispatch first -> clean tail
    int qt = (gridDim.x - 1) - blockIdx.x;
    int h = blockIdx.y, b = blockIdx.z;
    const float* Q = g_proj[0] + ((size_t)b * T + qt * 64) * E + h * 64;
    const float* K = g_proj[1] + (size_t)b * T * E + h * 64;
    const float* V = g_proj[2] + (size_t)b * T * E + h * 64;

    int tid = threadIdx.x, lane = tid & 31, wid = tid >> 5;
    int g = lane >> 2, t = lane & 3;

    auto loadK = [&](int kt) {
        const float* Kg = K + (size_t)(kt * 64) * E;
        #pragma unroll
        for (int i = 0; i < 8; i++) {
            int idx = tid + i * 128; int r = idx >> 4, c4 = idx & 15;
            cpasync16(&Kb[r * LDS_ + c4 * 4], Kg + (size_t)r * E + c4 * 4);
        }
        CP_COMMIT();
    };
    auto loadV = [&](int kt) {
        const float* Vg = V + (size_t)(kt * 64) * E;
        #pragma unroll
        for (int i = 0; i < 8; i++) {
            int idx = tid + i * 128; int r = idx >> 4, c4 = idx & 15;
            cpasync16(&Vb[r * LDS_ + c4 * 4], Vg + (size_t)r * E + c4 * 4);
        }
        CP_COMMIT();
    };

    // load Q tile (plain loads) + start K0, V0
    #pragma unroll
    for (int i = 0; i < 8; i++) {
        int idx = tid + i * 128; int r = idx >> 4, c4 = idx & 15;
        *(float4*)&QP[r * LDS_ + c4 * 4] = *(const float4*)(Q + (size_t)r * E + c4 * 4);
    }
    loadK(0);
    loadV(0);
    __syncthreads();   // Q visible to own-warp fragment extraction

    // Q fragments: x 2^-5 (exact); held in registers for whole loop
    uint32_t qf[8][4];
    {
        int mr = wid * 16;
        #pragma unroll
        for (int ks = 0; ks < 8; ks++) {
            int k0 = ks * 8;
            qf[ks][0] = __float_as_uint(QP[(mr + g)     * LDS_ + k0 + t]     * SCALE);
            qf[ks][1] = __float_as_uint(QP[(mr + g + 8) * LDS_ + k0 + t]     * SCALE);
            qf[ks][2] = __float_as_uint(QP[(mr + g)     * LDS_ + k0 + t + 4] * SCALE);
            qf[ks][3] = __float_as_uint(QP[(mr + g + 8) * LDS_ + k0 + t + 4] * SCALE);
        }
    }

    float o[8][4] = {};
    float m0 = -1e30f, m1 = -1e30f, l0 = 0.f, l1 = 0.f;
    int row0 = qt * 64 + wid * 16 + g;
    int pr = wid * 16 + g;

    for (int kt = 0; kt <= qt; kt++) {
        CP_WAIT1();        // K(kt) arrived (V(kt) may still be in flight)
        __syncthreads();

        // S = Q @ K^T  (16x64 per warp)
        float s[8][4] = {};
        #pragma unroll
        for (int ks = 0; ks < 8; ks++) {
            int k0 = ks * 8;
            #pragma unroll
            for (int nt = 0; nt < 8; nt++) {
                uint32_t bf[2];
                bf[0] = __float_as_uint(Kb[(nt * 8 + g) * LDS_ + k0 + t]);
                bf[1] = __float_as_uint(Kb[(nt * 8 + g) * LDS_ + k0 + t + 4]);
                mma8(s[nt], qf[ks], bf);
            }
        }

        if (kt == qt) {
            #pragma unroll
            for (int nt = 0; nt < 8; nt++) {
                int c = kt * 64 + nt * 8 + 2 * t;
                if (c     > row0)     s[nt][0] = -1e30f;
                if (c + 1 > row0)     s[nt][1] = -1e30f;
                if (c     > row0 + 8) s[nt][2] = -1e30f;
                if (c + 1 > row0 + 8) s[nt][3] = -1e30f;
            }
        }

        // online softmax
        float mx0 = -1e30f, mx1 = -1e30f;
        #pragma unroll
        for (int nt = 0; nt < 8; nt++) {
            mx0 = fmaxf(mx0, fmaxf(s[nt][0], s[nt][1]));
            mx1 = fmaxf(mx1, fmaxf(s[nt][2], s[nt][3]));
        }
        mx0 = fmaxf(mx0, __shfl_xor_sync(0xffffffffu, mx0, 1));
        mx0 = fmaxf(mx0, __shfl_xor_sync(0xffffffffu, mx0, 2));
        mx1 = fmaxf(mx1, __shfl_xor_sync(0xffffffffu, mx1, 1));
        mx1 = fmaxf(mx1, __shfl_xor_sync(0xffffffffu, mx1, 2));
        float mn0 = fmaxf(m0, mx0), mn1 = fmaxf(m1, mx1);
        float c0 = __expf(m0 - mn0), c1 = __expf(m1 - mn1);

        float ps0 = 0.f, ps1 = 0.f;
        #pragma unroll
        for (int nt = 0; nt < 8; nt++) {
            float p0 = __expf(s[nt][0] - mn0), p1 = __expf(s[nt][1] - mn0);
            float p2 = __expf(s[nt][2] - mn1), p3 = __expf(s[nt][3] - mn1);
            ps0 += p0 + p1; ps1 += p2 + p3;
            float2 w0 = {rtf(p0), rtf(p1)}, w1 = {rtf(p2), rtf(p3)};
            *(float2*)&QP[(size_t)pr * LDS_ + nt * 8 + 2 * t] = w0;
            *(float2*)&QP[(size_t)(pr + 8) * LDS_ + nt * 8 + 2 * t] = w1;
        }
        ps0 += __shfl_xor_sync(0xffffffffu, ps0, 1);
        ps0 += __shfl_xor_sync(0xffffffffu, ps0, 2);
        ps1 += __shfl_xor_sync(0xffffffffu, ps1, 1);
        ps1 += __shfl_xor_sync(0xffffffffu, ps1, 2);
        l0 = l0 * c0 + ps0; l1 = l1 * c1 + ps1;
        m0 = mn0; m1 = mn1;

        #pragma unroll
        for (int nt = 0; nt < 8; nt++) {
            o[nt][0] *= c0; o[nt][1] *= c0;
            o[nt][2] *= c1; o[nt][3] *= c1;
        }
        __syncwarp();      // own-row P visible to own warp

        CP_WAIT0();        // V(kt) arrived
        __syncthreads();   // + all warps done with K(kt)
        if (kt + 1 <= qt) loadK(kt + 1);   // overlaps with PV below

        // O += P @ V
        #pragma unroll
        for (int ks = 0; ks < 8; ks++) {
            int k0 = ks * 8;
            uint32_t af[4];
            af[0] = __float_as_uint(QP[(size_t)pr       * LDS_ + k0 + t]);
            af[1] = __float_as_uint(QP[(size_t)(pr + 8) * LDS_ + k0 + t]);
            af[2] = __float_as_uint(QP[(size_t)pr       * LDS_ + k0 + t + 4]);
            af[3] = __float_as_uint(QP[(size_t)(pr + 8) * LDS_ + k0 + t + 4]);
            #pragma unroll
            for (int nt = 0; nt < 8; nt++) {
                uint32_t bf[2];
                bf[0] = __float_as_uint(Vb[(k0 + t)     * LDS_ + nt * 8 + g]);
                bf[1] = __float_as_uint(Vb[(k0 + t + 4) * LDS_ + nt * 8 + g]);
                mma8(o[nt], af, bf);
            }
        }

        __syncthreads();   // all warps done with V(kt)
        if (kt + 1 <= qt) loadV(kt + 1);   // overlaps with next S phase
    }

    float i0 = 1.f / l0, i1 = 1.f / l1;
    float* O0 = g_att + ((size_t)b * T + row0) * E + h * 64;
    float* O1 = O0 + 8 * (size_t)E;
    #pragma unroll
    for (int nt = 0; nt < 8; nt++) {
        float2 w0 = {rtf(o[nt][0] * i0), rtf(o[nt][1] * i0)};
        float2 w1 = {rtf(o[nt][2] * i1), rtf(o[nt][3] * i1)};
        *(float2*)&O0[nt * 8 + 2 * t] = w0;
        *(float2*)&O1[nt * 8 + 2 * t] = w1;
    }
}

// ---------------- launch ----------------
extern "C" void kernel_launch(void* const* d_in, const int* in_sizes, int n_in,
                              void* d_out, int out_size)
{
    const float* v    = (const float*)d_in[0];
    const float* k    = (const float*)d_in[1];
    const float* q    = (const float*)d_in[2];
    const float* ln_g = (const float*)d_in[3];
    const float* ln_b = (const float*)d_in[4];
    const float* Wq   = (const float*)d_in[5];
    const float* Wk   = (const float*)d_in[6];
    const float* Wv   = (const float*)d_in[7];
    const float* Wp   = (const float*)d_in[8];
    const float* bp   = (const float*)d_in[9];
    float* out = (float*)d_out;

    cudaFuncSetAttribute(gemm_qkv, cudaFuncAttributeMaxDynamicSharedMemorySize, GEMM_SMEM);
    cudaFuncSetAttribute(gemm_out, cudaFuncAttributeMaxDynamicSharedMemorySize, GEMM_SMEM);
    cudaFuncSetAttribute(attn_tc,  cudaFuncAttributeMaxDynamicSharedMemorySize, ATT_SMEM);

    // 0) pre-round weights + LayerNorm
    round_w<<<dim3(E * E / 1024, 4), 256>>>(Wq, Wk, Wv, Wp);
    ln_kernel<<<dim3(BT, 3), 256>>>(q, k, v, ln_g, ln_b);

    // 1) QKV projections, fused into one launch (z = stream)
    gemm_qkv<<<dim3(E / BN, BT / BM, 3), 256, GEMM_SMEM>>>();

    // 2) causal flash attention (3-tile smem -> 3 CTAs/SM)
    attn_tc<<<dim3(T / 64, H, B), 128, ATT_SMEM>>>();

    // 3) output projection + bias -> d_out
    gemm_out<<<dim3(E / BN, BT / BM), 256, GEMM_SMEM>>>(bp, out);
}

// round 7
// speedup vs baseline: 1.0975x; 1.0446x over previous
#include <cuda_runtime.h>
#include <math.h>
#include <stdint.h>

// Problem constants
constexpr int B  = 4;
constexpr int T  = 1024;
constexpr int E  = 1024;
constexpr int H  = 16;
constexpr int BT = B * T;              // 4096 rows
constexpr float EPS = 1e-5f;
constexpr float SCALE = 0.03125f;      // E^-0.5 = 1/32

// ---------------- scratch (no cudaMalloc allowed) ----------------
__device__ float g_ln[3][BT * E];      // tf32-rounded LN outputs
__device__ float g_w[4][E * E];        // tf32-rounded weights (Wq,Wk,Wv,Wp)
__device__ float g_proj[3][BT * E];    // tf32-rounded projected q/k/v [bt][h*64+d]
__device__ float g_att[BT * E];        // tf32-rounded attention out [bt][e]

// ---------------- tf32 mma helpers ----------------
__device__ __forceinline__ uint32_t f2tf(float x) {
    uint32_t u; asm("cvt.rna.tf32.f32 %0, %1;" : "=r"(u) : "f"(x)); return u;
}
__device__ __forceinline__ float rtf(float x) { return __uint_as_float(f2tf(x)); }
__device__ __forceinline__ float ex2(float x) {
    float y; asm("ex2.approx.f32 %0, %1;" : "=f"(y) : "f"(x)); return y;
}
__device__ __forceinline__ void mma8(float* c, const uint32_t* a, const uint32_t* b) {
    asm volatile(
        "mma.sync.aligned.m16n8k8.row.col.f32.tf32.tf32.f32 "
        "{%0,%1,%2,%3}, {%4,%5,%6,%7}, {%8,%9}, {%0,%1,%2,%3};"
        : "+f"(c[0]), "+f"(c[1]), "+f"(c[2]), "+f"(c[3])
        : "r"(a[0]), "r"(a[1]), "r"(a[2]), "r"(a[3]), "r"(b[0]), "r"(b[1]));
}
__device__ __forceinline__ void cpasync16(void* s, const void* g) {
    uint32_t sa = (uint32_t)__cvta_generic_to_shared(s);
    asm volatile("cp.async.ca.shared.global [%0], [%1], 16;" :: "r"(sa), "l"(g));
}
#define CP_COMMIT() asm volatile("cp.async.commit_group;")
#define CP_WAIT0()  asm volatile("cp.async.wait_group 0;")
#define CP_WAIT1()  asm volatile("cp.async.wait_group 1;")

// ---------------- weight pre-round: 4 matrices -> g_w ----------------
__global__ void __launch_bounds__(256) round_w(
    const float* __restrict__ wq, const float* __restrict__ wk,
    const float* __restrict__ wv, const float* __restrict__ wp)
{
    int which = blockIdx.y;
    const float* src = (which == 0) ? wq : (which == 1) ? wk : (which == 2) ? wv : wp;
    float* dst = g_w[which];
    int i = (blockIdx.x * 256 + threadIdx.x) * 4;
    float4 v = *(const float4*)(src + i);
    v.x = rtf(v.x); v.y = rtf(v.y); v.z = rtf(v.z); v.w = rtf(v.w);
    *(float4*)(dst + i) = v;
}

// ---------------- block reduction helper ----------------
__device__ __forceinline__ float block_sum_256(float v) {
    __shared__ float sh[8];
    int tid = threadIdx.x;
    #pragma unroll
    for (int o = 16; o; o >>= 1) v += __shfl_xor_sync(0xffffffffu, v, o);
    if ((tid & 31) == 0) sh[tid >> 5] = v;
    __syncthreads();
    float r = (tid < 8) ? sh[tid] : 0.f;
    if (tid < 32) {
        #pragma unroll
        for (int o = 4; o; o >>= 1) r += __shfl_xor_sync(0xffffffffu, r, o);
        if (tid == 0) sh[0] = r;
    }
    __syncthreads();
    r = sh[0];
    __syncthreads();
    return r;
}

// ---------------- LayerNorm ----------------
__global__ void __launch_bounds__(256) ln_kernel(
    const float* __restrict__ q, const float* __restrict__ k,
    const float* __restrict__ v, const float* __restrict__ gamma,
    const float* __restrict__ beta)
{
    int stream = blockIdx.y;
    int row    = blockIdx.x;
    const float* x = (stream == 0) ? q : (stream == 1) ? k : v;
    float* y = g_ln[stream];
    x += (size_t)row * E;
    y += (size_t)row * E;
    int tid = threadIdx.x;

    float vals[4];
    float s = 0.f;
    #pragma unroll
    for (int i = 0; i < 4; i++) { vals[i] = x[tid + 256 * i]; s += vals[i]; }
    float mu = block_sum_256(s) * (1.f / E);

    float vs = 0.f;
    #pragma unroll
    for (int i = 0; i < 4; i++) { float d = vals[i] - mu; vs += d * d; }
    float var = block_sum_256(vs) * (1.f / E);
    float inv = rsqrtf(var + EPS);

    #pragma unroll
    for (int i = 0; i < 4; i++) {
        int e = tid + 256 * i;
        y[e] = rtf((vals[i] - mu) * inv * gamma[e] + beta[e]);
    }
}

// ---------------- TF32 tensor-core GEMM 128x128x32, 1-sync cp.async pipeline ----------------
constexpr int BM = 128, BN = 128, BK = 32;
constexpr int ASTRIDE = 36;
constexpr int BSTRIDE = 136;
constexpr int ABUF = BM * ASTRIDE;
constexpr int BBUF = BK * BSTRIDE;
constexpr int GEMM_SMEM = (2 * ABUF + 2 * BBUF) * (int)sizeof(float);  // 71680

template<bool OUT>
__device__ __forceinline__ void gemm_body(
    const float* __restrict__ A, const float* __restrict__ W,
    const float* __restrict__ bias, float* __restrict__ C)
{
    extern __shared__ float sm[];
    float* As = sm;              // [2][ABUF]
    float* Bs = sm + 2 * ABUF;   // [2][BBUF]

    int m0 = blockIdx.y * BM, n0 = blockIdx.x * BN;
    int tid = threadIdx.x, lane = tid & 31, wid = tid >> 5;
    int g = lane >> 2, t = lane & 3;
    int wm = (wid & 1) * 64, wn = (wid >> 1) * 32;

    auto load_tiles = [&](int buf, int k0) {
        #pragma unroll
        for (int i = 0; i < 4; i++) {
            int idx = tid + i * 256; int r = idx >> 3, c4 = idx & 7;
            cpasync16(&As[buf * ABUF + r * ASTRIDE + c4 * 4],
                      A + (size_t)(m0 + r) * E + k0 + c4 * 4);
        }
        #pragma unroll
        for (int i = 0; i < 4; i++) {
            int idx = tid + i * 256; int r = idx >> 5, c4 = idx & 31;
            cpasync16(&Bs[buf * BBUF + r * BSTRIDE + c4 * 4],
                      W + (size_t)(k0 + r) * E + n0 + c4 * 4);
        }
        CP_COMMIT();
    };

    float acc[4][4][4] = {};
    load_tiles(0, 0);

    for (int kt = 0; kt < E / BK; kt++) {
        CP_WAIT0();
        __syncthreads();
        if (kt + 1 < E / BK) load_tiles((kt + 1) & 1, (kt + 1) * BK);
        const float* a_ = &As[(kt & 1) * ABUF];
        const float* b_ = &Bs[(kt & 1) * BBUF];
        #pragma unroll
        for (int ks = 0; ks < 4; ks++) {
            int k0 = ks * 8;
            uint32_t af[4][4], bf[4][2];
            #pragma unroll
            for (int mt = 0; mt < 4; mt++) {
                int mr = wm + mt * 16;
                af[mt][0] = __float_as_uint(a_[(mr + g)     * ASTRIDE + k0 + t]);
                af[mt][1] = __float_as_uint(a_[(mr + g + 8) * ASTRIDE + k0 + t]);
                af[mt][2] = __float_as_uint(a_[(mr + g)     * ASTRIDE + k0 + t + 4]);
                af[mt][3] = __float_as_uint(a_[(mr + g + 8) * ASTRIDE + k0 + t + 4]);
            }
            #pragma unroll
            for (int nt = 0; nt < 4; nt++) {
                int nc = wn + nt * 8 + g;
                bf[nt][0] = __float_as_uint(b_[(k0 + t)     * BSTRIDE + nc]);
                bf[nt][1] = __float_as_uint(b_[(k0 + t + 4) * BSTRIDE + nc]);
            }
            #pragma unroll
            for (int mt = 0; mt < 4; mt++)
                #pragma unroll
                for (int nt = 0; nt < 4; nt++)
                    mma8(acc[mt][nt], af[mt], bf[nt]);
        }
    }

    #pragma unroll
    for (int mt = 0; mt < 4; mt++) {
        int r0 = m0 + wm + mt * 16 + g;
        #pragma unroll
        for (int nt = 0; nt < 4; nt++) {
            int c0 = n0 + wn + nt * 8 + 2 * t;
            float2 v;
            if (OUT) {
                float b0 = bias[c0], b1 = bias[c0 + 1];
                v.x = acc[mt][nt][0] + b0; v.y = acc[mt][nt][1] + b1;
                *(float2*)&C[(size_t)r0 * E + c0] = v;
                v.x = acc[mt][nt][2] + b0; v.y = acc[mt][nt][3] + b1;
                *(float2*)&C[(size_t)(r0 + 8) * E + c0] = v;
            } else {
                v.x = rtf(acc[mt][nt][0]); v.y = rtf(acc[mt][nt][1]);
                *(float2*)&C[(size_t)r0 * E + c0] = v;
                v.x = rtf(acc[mt][nt][2]); v.y = rtf(acc[mt][nt][3]);
                *(float2*)&C[(size_t)(r0 + 8) * E + c0] = v;
            }
        }
    }
}

__global__ void __launch_bounds__(256, 2) gemm_qkv() {
    int z = blockIdx.z;
    gemm_body<false>(g_ln[z], g_w[z], nullptr, g_proj[z]);
}
__global__ void __launch_bounds__(256, 2) gemm_out(
    const float* __restrict__ bias, float* __restrict__ Cext) {
    gemm_body<true>(g_att, g_w[3], bias, Cext);
}

// ---------------- flash attention: 128-row Q tile, 2 m-tiles per warp ----------------
constexpr int LDS_ = 68;
constexpr int QROWS = 128;
constexpr int KVT = 64 * LDS_;                              // one 64x64 tile (floats)
constexpr int ATT_SMEM = (QROWS + 128) * LDS_ * (int)sizeof(float);  // QP128 + K + V = 69632

__global__ void __launch_bounds__(128, 2) attn_tc() {
    extern __shared__ float sm[];
    float* QP = sm;                    // 128 x 68: Q, then P
    float* Kb = sm + QROWS * LDS_;
    float* Vb = Kb + KVT;

    int qt = (gridDim.x - 1) - blockIdx.x;   // descending work order
    int h = blockIdx.y, b = blockIdx.z;
    const float* Q = g_proj[0] + ((size_t)b * T + qt * QROWS) * E + h * 64;
    const float* K = g_proj[1] + (size_t)b * T * E + h * 64;
    const float* V = g_proj[2] + (size_t)b * T * E + h * 64;

    int tid = threadIdx.x, lane = tid & 31, wid = tid >> 5;
    int g = lane >> 2, t = lane & 3;

    auto loadK = [&](int kt) {
        const float* Kg = K + (size_t)(kt * 64) * E;
        #pragma unroll
        for (int i = 0; i < 8; i++) {
            int idx = tid + i * 128; int r = idx >> 4, c4 = idx & 15;
            cpasync16(&Kb[r * LDS_ + c4 * 4], Kg + (size_t)r * E + c4 * 4);
        }
        CP_COMMIT();
    };
    auto loadV = [&](int kt) {
        const float* Vg = V + (size_t)(kt * 64) * E;
        #pragma unroll
        for (int i = 0; i < 8; i++) {
            int idx = tid + i * 128; int r = idx >> 4, c4 = idx & 15;
            cpasync16(&Vb[r * LDS_ + c4 * 4], Vg + (size_t)r * E + c4 * 4);
        }
        CP_COMMIT();
    };

    // load Q tile 128x64 (plain loads), start K0/V0
    #pragma unroll
    for (int i = 0; i < 16; i++) {
        int idx = tid + i * 128; int r = idx >> 4, c4 = idx & 15;
        *(float4*)&QP[r * LDS_ + c4 * 4] = *(const float4*)(Q + (size_t)r * E + c4 * 4);
    }
    loadK(0);
    loadV(0);
    __syncthreads();

    // Q fragments for both m-tiles, scaled by SCALE*log2e (re-round to tf32)
    const float QS = SCALE * 1.44269504f;
    uint32_t qf0[8][4], qf1[8][4];
    int mr0 = wid * 16, mr1 = 64 + wid * 16;
    #pragma unroll
    for (int ks = 0; ks < 8; ks++) {
        int k0 = ks * 8;
        qf0[ks][0] = f2tf(QP[(mr0 + g)     * LDS_ + k0 + t]     * QS);
        qf0[ks][1] = f2tf(QP[(mr0 + g + 8) * LDS_ + k0 + t]     * QS);
        qf0[ks][2] = f2tf(QP[(mr0 + g)     * LDS_ + k0 + t + 4] * QS);
        qf0[ks][3] = f2tf(QP[(mr0 + g + 8) * LDS_ + k0 + t + 4] * QS);
        qf1[ks][0] = f2tf(QP[(mr1 + g)     * LDS_ + k0 + t]     * QS);
        qf1[ks][1] = f2tf(QP[(mr1 + g + 8) * LDS_ + k0 + t]     * QS);
        qf1[ks][2] = f2tf(QP[(mr1 + g)     * LDS_ + k0 + t + 4] * QS);
        qf1[ks][3] = f2tf(QP[(mr1 + g + 8) * LDS_ + k0 + t + 4] * QS);
    }

    float o0[8][4] = {}, o1[8][4] = {};
    float m0a = -1e30f, m0b = -1e30f, l0a = 0.f, l0b = 0.f;  // mtile0 rows g, g+8
    float m1a = -1e30f, m1b = -1e30f, l1a = 0.f, l1b = 0.f;  // mtile1
    int pr0 = mr0 + g, pr1 = mr1 + g;
    int row0 = qt * QROWS + pr0, row1 = qt * QROWS + pr1;
    int nkv = 2 * qt + 2;

    // softmax update for one m-tile (log2 domain, P written to QP rows pr/pr+8)
    auto softmax_upd = [&](float (&s)[8][4], float (&o)[8][4],
                           float& ma, float& mb, float& la, float& lb, int pr) {
        float mxa = -1e30f, mxb = -1e30f;
        #pragma unroll
        for (int nt = 0; nt < 8; nt++) {
            mxa = fmaxf(mxa, fmaxf(s[nt][0], s[nt][1]));
            mxb = fmaxf(mxb, fmaxf(s[nt][2], s[nt][3]));
        }
        mxa = fmaxf(mxa, __shfl_xor_sync(0xffffffffu, mxa, 1));
        mxa = fmaxf(mxa, __shfl_xor_sync(0xffffffffu, mxa, 2));
        mxb = fmaxf(mxb, __shfl_xor_sync(0xffffffffu, mxb, 1));
        mxb = fmaxf(mxb, __shfl_xor_sync(0xffffffffu, mxb, 2));
        float mna = fmaxf(ma, mxa), mnb = fmaxf(mb, mxb);
        float ca = ex2(ma - mna), cb = ex2(mb - mnb);
        float psa = 0.f, psb = 0.f;
        #pragma unroll
        for (int nt = 0; nt < 8; nt++) {
            float p0 = ex2(s[nt][0] - mna), p1 = ex2(s[nt][1] - mna);
            float p2 = ex2(s[nt][2] - mnb), p3 = ex2(s[nt][3] - mnb);
            psa += p0 + p1; psb += p2 + p3;
            float2 w0 = {rtf(p0), rtf(p1)}, w1 = {rtf(p2), rtf(p3)};
            *(float2*)&QP[(size_t)pr * LDS_ + nt * 8 + 2 * t] = w0;
            *(float2*)&QP[(size_t)(pr + 8) * LDS_ + nt * 8 + 2 * t] = w1;
        }
        psa += __shfl_xor_sync(0xffffffffu, psa, 1);
        psa += __shfl_xor_sync(0xffffffffu, psa, 2);
        psb += __shfl_xor_sync(0xffffffffu, psb, 1);
        psb += __shfl_xor_sync(0xffffffffu, psb, 2);
        la = la * ca + psa; lb = lb * cb + psb;
        ma = mna; mb = mnb;
        #pragma unroll
        for (int nt = 0; nt < 8; nt++) {
            o[nt][0] *= ca; o[nt][1] *= ca;
            o[nt][2] *= cb; o[nt][3] *= cb;
        }
    };

    for (int kt = 0; kt < nkv; kt++) {
        CP_WAIT1();          // K(kt) arrived
        __syncthreads();

        // S = Q @ K^T for both m-tiles (K fragment shared)
        float s0[8][4] = {}, s1[8][4] = {};
        #pragma unroll
        for (int ks = 0; ks < 8; ks++) {
            int k0 = ks * 8;
            #pragma unroll
            for (int nt = 0; nt < 8; nt++) {
                uint32_t bf[2];
                bf[0] = __float_as_uint(Kb[(nt * 8 + g) * LDS_ + k0 + t]);
                bf[1] = __float_as_uint(Kb[(nt * 8 + g) * LDS_ + k0 + t + 4]);
                mma8(s0[nt], qf0[ks], bf);
                mma8(s1[nt], qf1[ks], bf);
            }
        }

        // causal masking
        if (kt == 2 * qt) {           // diagonal for mtile0; mtile1 unmasked
            #pragma unroll
            for (int nt = 0; nt < 8; nt++) {
                int c = kt * 64 + nt * 8 + 2 * t;
                if (c     > row0)     s0[nt][0] = -1e30f;
                if (c + 1 > row0)     s0[nt][1] = -1e30f;
                if (c     > row0 + 8) s0[nt][2] = -1e30f;
                if (c + 1 > row0 + 8) s0[nt][3] = -1e30f;
            }
        } else if (kt == 2 * qt + 1) { // mtile0 fully masked; diagonal for mtile1
            #pragma unroll
            for (int nt = 0; nt < 8; nt++) {
                s0[nt][0] = s0[nt][1] = s0[nt][2] = s0[nt][3] = -1e30f;
                int c = kt * 64 + nt * 8 + 2 * t;
                if (c     > row1)     s1[nt][0] = -1e30f;
                if (c + 1 > row1)     s1[nt][1] = -1e30f;
                if (c     > row1 + 8) s1[nt][2] = -1e30f;
                if (c + 1 > row1 + 8) s1[nt][3] = -1e30f;
            }
        }

        softmax_upd(s0, o0, m0a, m0b, l0a, l0b, pr0);
        softmax_upd(s1, o1, m1a, m1b, l1a, l1b, pr1);
        __syncwarp();

        CP_WAIT0();          // V(kt) arrived
        __syncthreads();     // + all warps done with K(kt)
        if (kt + 1 < nkv) loadK(kt + 1);    // overlaps PV

        // O += P @ V for both m-tiles (V fragment shared)
        #pragma unroll
        for (int ks = 0; ks < 8; ks++) {
            int k0 = ks * 8;
            uint32_t af0[4], af1[4];
            af0[0] = __float_as_uint(QP[(size_t)pr0       * LDS_ + k0 + t]);
            af0[1] = __float_as_uint(QP[(size_t)(pr0 + 8) * LDS_ + k0 + t]);
            af0[2] = __float_as_uint(QP[(size_t)pr0       * LDS_ + k0 + t + 4]);
            af0[3] = __float_as_uint(QP[(size_t)(pr0 + 8) * LDS_ + k0 + t + 4]);
            af1[0] = __float_as_uint(QP[(size_t)pr1       * LDS_ + k0 + t]);
            af1[1] = __float_as_uint(QP[(size_t)(pr1 + 8) * LDS_ + k0 + t]);
            af1[2] = __float_as_uint(QP[(size_t)pr1       * LDS_ + k0 + t + 4]);
            af1[3] = __float_as_uint(QP[(size_t)(pr1 + 8) * LDS_ + k0 + t + 4]);
            #pragma unroll
            for (int nt = 0; nt < 8; nt++) {
                uint32_t bf[2];
                bf[0] = __float_as_uint(Vb[(k0 + t)     * LDS_ + nt * 8 + g]);
                bf[1] = __float_as_uint(Vb[(k0 + t + 4) * LDS_ + nt * 8 + g]);
                mma8(o0[nt], af0, bf);
                mma8(o1[nt], af1, bf);
            }
        }

        __syncthreads();     // all warps done with V(kt)
        if (kt + 1 < nkv) loadV(kt + 1);    // overlaps next S
    }

    float i0a = 1.f / l0a, i0b = 1.f / l0b;
    float i1a = 1.f / l1a, i1b = 1.f / l1b;
    float* O0 = g_att + ((size_t)b * T + row0) * E + h * 64;
    float* O1 = g_att + ((size_t)b * T + row1) * E + h * 64;
    #pragma unroll
    for (int nt = 0; nt < 8; nt++) {
        float2 w;
        w = {rtf(o0[nt][0] * i0a), rtf(o0[nt][1] * i0a)};
        *(float2*)&O0[nt * 8 + 2 * t] = w;
        w = {rtf(o0[nt][2] * i0b), rtf(o0[nt][3] * i0b)};
        *(float2*)&O0[8 * (size_t)E + nt * 8 + 2 * t] = w;
        w = {rtf(o1[nt][0] * i1a), rtf(o1[nt][1] * i1a)};
        *(float2*)&O1[nt * 8 + 2 * t] = w;
        w = {rtf(o1[nt][2] * i1b), rtf(o1[nt][3] * i1b)};
        *(float2*)&O1[8 * (size_t)E + nt * 8 + 2 * t] = w;
    }
}

// ---------------- launch ----------------
extern "C" void kernel_launch(void* const* d_in, const int* in_sizes, int n_in,
                              void* d_out, int out_size)
{
    const float* v    = (const float*)d_in[0];
    const float* k    = (const float*)d_in[1];
    const float* q    = (const float*)d_in[2];
    const float* ln_g = (const float*)d_in[3];
    const float* ln_b = (const float*)d_in[4];
    const float* Wq   = (const float*)d_in[5];
    const float* Wk   = (const float*)d_in[6];
    const float* Wv   = (const float*)d_in[7];
    const float* Wp   = (const float*)d_in[8];
    const float* bp   = (const float*)d_in[9];
    float* out = (float*)d_out;

    cudaFuncSetAttribute(gemm_qkv, cudaFuncAttributeMaxDynamicSharedMemorySize, GEMM_SMEM);
    cudaFuncSetAttribute(gemm_out, cudaFuncAttributeMaxDynamicSharedMemorySize, GEMM_SMEM);
    cudaFuncSetAttribute(attn_tc,  cudaFuncAttributeMaxDynamicSharedMemorySize, ATT_SMEM);

    // 0) pre-round weights + LayerNorm
    round_w<<<dim3(E * E / 1024, 4), 256>>>(Wq, Wk, Wv, Wp);
    ln_kernel<<<dim3(BT, 3), 256>>>(q, k, v, ln_g, ln_b);

    // 1) QKV projections, fused into one launch (z = stream)
    gemm_qkv<<<dim3(E / BN, BT / BM, 3), 256, GEMM_SMEM>>>();

    // 2) causal flash attention (128-row Q tiles, 2 m-tiles/warp)
    attn_tc<<<dim3(T / QROWS, H, B), 128, ATT_SMEM>>>();

    // 3) output projection + bias -> d_out
    gemm_out<<<dim3(E / BN, BT / BM), 256, GEMM_SMEM>>>(bp, out);
}

// round 8
// speedup vs baseline: 1.1332x; 1.0325x over previous
#include <cuda_runtime.h>
#include <math.h>
#include <stdint.h>

// Problem constants
constexpr int B  = 4;
constexpr int T  = 1024;
constexpr int E  = 1024;
constexpr int H  = 16;
constexpr int BT = B * T;              // 4096 rows
constexpr float EPS = 1e-5f;
constexpr float SCALE = 0.03125f;      // E^-0.5 = 1/32

// ---------------- scratch (no cudaMalloc allowed) ----------------
__device__ float g_ln[3][BT * E];      // tf32-rounded LN outputs
__device__ float g_w[4][E * E];        // tf32-rounded weights (Wq,Wk,Wv,Wp)
__device__ float g_proj[3][BT * E];    // tf32-rounded projected q/k/v [bt][h*64+d]
__device__ float g_att[BT * E];        // tf32-rounded attention out [bt][e]

// ---------------- tf32 mma helpers ----------------
__device__ __forceinline__ uint32_t f2tf(float x) {
    uint32_t u; asm("cvt.rna.tf32.f32 %0, %1;" : "=r"(u) : "f"(x)); return u;
}
__device__ __forceinline__ float rtf(float x) { return __uint_as_float(f2tf(x)); }
__device__ __forceinline__ float ex2(float x) {
    float y; asm("ex2.approx.f32 %0, %1;" : "=f"(y) : "f"(x)); return y;
}
__device__ __forceinline__ void mma8(float* c, const uint32_t* a, const uint32_t* b) {
    asm volatile(
        "mma.sync.aligned.m16n8k8.row.col.f32.tf32.tf32.f32 "
        "{%0,%1,%2,%3}, {%4,%5,%6,%7}, {%8,%9}, {%0,%1,%2,%3};"
        : "+f"(c[0]), "+f"(c[1]), "+f"(c[2]), "+f"(c[3])
        : "r"(a[0]), "r"(a[1]), "r"(a[2]), "r"(a[3]), "r"(b[0]), "r"(b[1]));
}
__device__ __forceinline__ void cpasync16(void* s, const void* g) {
    uint32_t sa = (uint32_t)__cvta_generic_to_shared(s);
    asm volatile("cp.async.ca.shared.global [%0], [%1], 16;" :: "r"(sa), "l"(g));
}
#define CP_COMMIT() asm volatile("cp.async.commit_group;")
#define CP_WAIT0()  asm volatile("cp.async.wait_group 0;")
#define CP_WAIT1()  asm volatile("cp.async.wait_group 1;")

// ---------------- weight pre-round: 4 matrices -> g_w ----------------
__global__ void __launch_bounds__(256) round_w(
    const float* __restrict__ wq, const float* __restrict__ wk,
    const float* __restrict__ wv, const float* __restrict__ wp)
{
    int which = blockIdx.y;
    const float* src = (which == 0) ? wq : (which == 1) ? wk : (which == 2) ? wv : wp;
    float* dst = g_w[which];
    int i = (blockIdx.x * 256 + threadIdx.x) * 4;
    float4 v = *(const float4*)(src + i);
    v.x = rtf(v.x); v.y = rtf(v.y); v.z = rtf(v.z); v.w = rtf(v.w);
    *(float4*)(dst + i) = v;
}

// ---------------- block reduction helper ----------------
__device__ __forceinline__ float block_sum_256(float v) {
    __shared__ float sh[8];
    int tid = threadIdx.x;
    #pragma unroll
    for (int o = 16; o; o >>= 1) v += __shfl_xor_sync(0xffffffffu, v, o);
    if ((tid & 31) == 0) sh[tid >> 5] = v;
    __syncthreads();
    float r = (tid < 8) ? sh[tid] : 0.f;
    if (tid < 32) {
        #pragma unroll
        for (int o = 4; o; o >>= 1) r += __shfl_xor_sync(0xffffffffu, r, o);
        if (tid == 0) sh[0] = r;
    }
    __syncthreads();
    r = sh[0];
    __syncthreads();
    return r;
}

// ---------------- LayerNorm ----------------
__global__ void __launch_bounds__(256) ln_kernel(
    const float* __restrict__ q, const float* __restrict__ k,
    const float* __restrict__ v, const float* __restrict__ gamma,
    const float* __restrict__ beta)
{
    int stream = blockIdx.y;
    int row    = blockIdx.x;
    const float* x = (stream == 0) ? q : (stream == 1) ? k : v;
    float* y = g_ln[stream];
    x += (size_t)row * E;
    y += (size_t)row * E;
    int tid = threadIdx.x;

    float vals[4];
    float s = 0.f;
    #pragma unroll
    for (int i = 0; i < 4; i++) { vals[i] = x[tid + 256 * i]; s += vals[i]; }
    float mu = block_sum_256(s) * (1.f / E);

    float vs = 0.f;
    #pragma unroll
    for (int i = 0; i < 4; i++) { float d = vals[i] - mu; vs += d * d; }
    float var = block_sum_256(vs) * (1.f / E);
    float inv = rsqrtf(var + EPS);

    #pragma unroll
    for (int i = 0; i < 4; i++) {
        int e = tid + 256 * i;
        y[e] = rtf((vals[i] - mu) * inv * gamma[e] + beta[e]);
    }
}

// ---------------- TF32 GEMM: CTA 128x256x32, warp tile 64x64 (128 B LDS / MMA) ----------------
constexpr int BM = 128, BN = 256, BK = 32;
constexpr int ASTRIDE = 36;    // 4g+t bank pattern, conflict-free
constexpr int BSTRIDE = 264;   // 264 mod 32 = 8 -> 8t+g pattern, conflict-free
constexpr int ABUF = BM * ASTRIDE;   // 4608
constexpr int BBUF = BK * BSTRIDE;   // 8448
constexpr int GEMM_SMEM = (2 * ABUF + 2 * BBUF) * (int)sizeof(float);  // 104448

template<bool OUT>
__device__ __forceinline__ void gemm_body(
    const float* __restrict__ A, const float* __restrict__ W,
    const float* __restrict__ bias, float* __restrict__ C)
{
    extern __shared__ float sm[];
    float* As = sm;              // [2][ABUF]
    float* Bs = sm + 2 * ABUF;   // [2][BBUF]

    int m0 = blockIdx.y * BM, n0 = blockIdx.x * BN;
    int tid = threadIdx.x, lane = tid & 31, wid = tid >> 5;
    int g = lane >> 2, t = lane & 3;
    int wm = (wid & 1) * 64, wn = (wid >> 1) * 64;

    auto load_tiles = [&](int buf, int k0) {
        #pragma unroll
        for (int i = 0; i < 4; i++) {
            int idx = tid + i * 256; int r = idx >> 3, c4 = idx & 7;
            cpasync16(&As[buf * ABUF + r * ASTRIDE + c4 * 4],
                      A + (size_t)(m0 + r) * E + k0 + c4 * 4);
        }
        #pragma unroll
        for (int i = 0; i < 8; i++) {
            int idx = tid + i * 256; int r = idx >> 6, c4 = idx & 63;
            cpasync16(&Bs[buf * BBUF + r * BSTRIDE + c4 * 4],
                      W + (size_t)(k0 + r) * E + n0 + c4 * 4);
        }
        CP_COMMIT();
    };

    float acc[4][8][4] = {};
    load_tiles(0, 0);

    for (int kt = 0; kt < E / BK; kt++) {
        CP_WAIT0();
        __syncthreads();
        if (kt + 1 < E / BK) load_tiles((kt + 1) & 1, (kt + 1) * BK);
        const float* a_ = &As[(kt & 1) * ABUF];
        const float* b_ = &Bs[(kt & 1) * BBUF];
        #pragma unroll
        for (int ks = 0; ks < 4; ks++) {
            int k0 = ks * 8;
            uint32_t af[4][4], bf[8][2];
            #pragma unroll
            for (int mt = 0; mt < 4; mt++) {
                int mr = wm + mt * 16;
                af[mt][0] = __float_as_uint(a_[(mr + g)     * ASTRIDE + k0 + t]);
                af[mt][1] = __float_as_uint(a_[(mr + g + 8) * ASTRIDE + k0 + t]);
                af[mt][2] = __float_as_uint(a_[(mr + g)     * ASTRIDE + k0 + t + 4]);
                af[mt][3] = __float_as_uint(a_[(mr + g + 8) * ASTRIDE + k0 + t + 4]);
            }
            #pragma unroll
            for (int nt = 0; nt < 8; nt++) {
                int nc = wn + nt * 8 + g;
                bf[nt][0] = __float_as_uint(b_[(k0 + t)     * BSTRIDE + nc]);
                bf[nt][1] = __float_as_uint(b_[(k0 + t + 4) * BSTRIDE + nc]);
            }
            #pragma unroll
            for (int mt = 0; mt < 4; mt++)
                #pragma unroll
                for (int nt = 0; nt < 8; nt++)
                    mma8(acc[mt][nt], af[mt], bf[nt]);
        }
    }

    #pragma unroll
    for (int mt = 0; mt < 4; mt++) {
        int r0 = m0 + wm + mt * 16 + g;
        #pragma unroll
        for (int nt = 0; nt < 8; nt++) {
            int c0 = n0 + wn + nt * 8 + 2 * t;
            float2 v;
            if (OUT) {
                float b0 = bias[c0], b1 = bias[c0 + 1];
                v.x = acc[mt][nt][0] + b0; v.y = acc[mt][nt][1] + b1;
                *(float2*)&C[(size_t)r0 * E + c0] = v;
                v.x = acc[mt][nt][2] + b0; v.y = acc[mt][nt][3] + b1;
                *(float2*)&C[(size_t)(r0 + 8) * E + c0] = v;
            } else {
                v.x = rtf(acc[mt][nt][0]); v.y = rtf(acc[mt][nt][1]);
                *(float2*)&C[(size_t)r0 * E + c0] = v;
                v.x = rtf(acc[mt][nt][2]); v.y = rtf(acc[mt][nt][3]);
                *(float2*)&C[(size_t)(r0 + 8) * E + c0] = v;
            }
        }
    }
}

__global__ void __launch_bounds__(256, 1) gemm_qkv() {
    int z = blockIdx.z;
    gemm_body<false>(g_ln[z], g_w[z], nullptr, g_proj[z]);
}
__global__ void __launch_bounds__(256, 1) gemm_out(
    const float* __restrict__ bias, float* __restrict__ Cext) {
    gemm_body<true>(g_att, g_w[3], bias, Cext);
}

// ---------------- flash attention: 128-row Q tile, 2 m-tiles per warp ----------------
constexpr int LDS_ = 68;
constexpr int QROWS = 128;
constexpr int KVT = 64 * LDS_;                              // one 64x64 tile (floats)
constexpr int ATT_SMEM = (QROWS + 128) * LDS_ * (int)sizeof(float);  // 69632

__global__ void __launch_bounds__(128, 2) attn_tc() {
    extern __shared__ float sm[];
    float* QP = sm;                    // 128 x 68: Q, then P
    float* Kb = sm + QROWS * LDS_;
    float* Vb = Kb + KVT;

    int qt = (gridDim.x - 1) - blockIdx.x;   // descending work order
    int h = blockIdx.y, b = blockIdx.z;
    const float* Q = g_proj[0] + ((size_t)b * T + qt * QROWS) * E + h * 64;
    const float* K = g_proj[1] + (size_t)b * T * E + h * 64;
    const float* V = g_proj[2] + (size_t)b * T * E + h * 64;

    int tid = threadIdx.x, lane = tid & 31, wid = tid >> 5;
    int g = lane >> 2, t = lane & 3;

    auto loadK = [&](int kt) {
        const float* Kg = K + (size_t)(kt * 64) * E;
        #pragma unroll
        for (int i = 0; i < 8; i++) {
            int idx = tid + i * 128; int r = idx >> 4, c4 = idx & 15;
            cpasync16(&Kb[r * LDS_ + c4 * 4], Kg + (size_t)r * E + c4 * 4);
        }
        CP_COMMIT();
    };
    auto loadV = [&](int kt) {
        const float* Vg = V + (size_t)(kt * 64) * E;
        #pragma unroll
        for (int i = 0; i < 8; i++) {
            int idx = tid + i * 128; int r = idx >> 4, c4 = idx & 15;
            cpasync16(&Vb[r * LDS_ + c4 * 4], Vg + (size_t)r * E + c4 * 4);
        }
        CP_COMMIT();
    };

    // load Q tile 128x64 (plain loads), start K0/V0
    #pragma unroll
    for (int i = 0; i < 16; i++) {
        int idx = tid + i * 128; int r = idx >> 4, c4 = idx & 15;
        *(float4*)&QP[r * LDS_ + c4 * 4] = *(const float4*)(Q + (size_t)r * E + c4 * 4);
    }
    loadK(0);
    loadV(0);
    __syncthreads();

    // Q fragments for both m-tiles, scaled by SCALE*log2e (re-round to tf32)
    const float QS = SCALE * 1.44269504f;
    uint32_t qf0[8][4], qf1[8][4];
    int mr0 = wid * 16, mr1 = 64 + wid * 16;
    #pragma unroll
    for (int ks = 0; ks < 8; ks++) {
        int k0 = ks * 8;
        qf0[ks][0] = f2tf(QP[(mr0 + g)     * LDS_ + k0 + t]     * QS);
        qf0[ks][1] = f2tf(QP[(mr0 + g + 8) * LDS_ + k0 + t]     * QS);
        qf0[ks][2] = f2tf(QP[(mr0 + g)     * LDS_ + k0 + t + 4] * QS);
        qf0[ks][3] = f2tf(QP[(mr0 + g + 8) * LDS_ + k0 + t + 4] * QS);
        qf1[ks][0] = f2tf(QP[(mr1 + g)     * LDS_ + k0 + t]     * QS);
        qf1[ks][1] = f2tf(QP[(mr1 + g + 8) * LDS_ + k0 + t]     * QS);
        qf1[ks][2] = f2tf(QP[(mr1 + g)     * LDS_ + k0 + t + 4] * QS);
        qf1[ks][3] = f2tf(QP[(mr1 + g + 8) * LDS_ + k0 + t + 4] * QS);
    }

    float o0[8][4] = {}, o1[8][4] = {};
    float m0a = -1e30f, m0b = -1e30f, l0a = 0.f, l0b = 0.f;
    float m1a = -1e30f, m1b = -1e30f, l1a = 0.f, l1b = 0.f;
    int pr0 = mr0 + g, pr1 = mr1 + g;
    int row0 = qt * QROWS + pr0, row1 = qt * QROWS + pr1;
    int nkv = 2 * qt + 2;

    auto softmax_upd = [&](float (&s)[8][4], float (&o)[8][4],
                           float& ma, float& mb, float& la, float& lb, int pr) {
        float mxa = -1e30f, mxb = -1e30f;
        #pragma unroll
        for (int nt = 0; nt < 8; nt++) {
            mxa = fmaxf(mxa, fmaxf(s[nt][0], s[nt][1]));
            mxb = fmaxf(mxb, fmaxf(s[nt][2], s[nt][3]));
        }
        mxa = fmaxf(mxa, __shfl_xor_sync(0xffffffffu, mxa, 1));
        mxa = fmaxf(mxa, __shfl_xor_sync(0xffffffffu, mxa, 2));
        mxb = fmaxf(mxb, __shfl_xor_sync(0xffffffffu, mxb, 1));
        mxb = fmaxf(mxb, __shfl_xor_sync(0xffffffffu, mxb, 2));
        float mna = fmaxf(ma, mxa), mnb = fmaxf(mb, mxb);
        float ca = ex2(ma - mna), cb = ex2(mb - mnb);
        float psa = 0.f, psb = 0.f;
        #pragma unroll
        for (int nt = 0; nt < 8; nt++) {
            float p0 = ex2(s[nt][0] - mna), p1 = ex2(s[nt][1] - mna);
            float p2 = ex2(s[nt][2] - mnb), p3 = ex2(s[nt][3] - mnb);
            psa += p0 + p1; psb += p2 + p3;
            float2 w0 = {rtf(p0), rtf(p1)}, w1 = {rtf(p2), rtf(p3)};
            *(float2*)&QP[(size_t)pr * LDS_ + nt * 8 + 2 * t] = w0;
            *(float2*)&QP[(size_t)(pr + 8) * LDS_ + nt * 8 + 2 * t] = w1;
        }
        psa += __shfl_xor_sync(0xffffffffu, psa, 1);
        psa += __shfl_xor_sync(0xffffffffu, psa, 2);
        psb += __shfl_xor_sync(0xffffffffu, psb, 1);
        psb += __shfl_xor_sync(0xffffffffu, psb, 2);
        la = la * ca + psa; lb = lb * cb + psb;
        ma = mna; mb = mnb;
        #pragma unroll
        for (int nt = 0; nt < 8; nt++) {
            o[nt][0] *= ca; o[nt][1] *= ca;
            o[nt][2] *= cb; o[nt][3] *= cb;
        }
    };

    for (int kt = 0; kt < nkv; kt++) {
        CP_WAIT1();
        __syncthreads();

        float s0[8][4] = {}, s1[8][4] = {};
        #pragma unroll
        for (int ks = 0; ks < 8; ks++) {
            int k0 = ks * 8;
            #pragma unroll
            for (int nt = 0; nt < 8; nt++) {
                uint32_t bf[2];
                bf[0] = __float_as_uint(Kb[(nt * 8 + g) * LDS_ + k0 + t]);
                bf[1] = __float_as_uint(Kb[(nt * 8 + g) * LDS_ + k0 + t + 4]);
                mma8(s0[nt], qf0[ks], bf);
                mma8(s1[nt], qf1[ks], bf);
            }
        }

        if (kt == 2 * qt) {
            #pragma unroll
            for (int nt = 0; nt < 8; nt++) {
                int c = kt * 64 + nt * 8 + 2 * t;
                if (c     > row0)     s0[nt][0] = -1e30f;
                if (c + 1 > row0)     s0[nt][1] = -1e30f;
                if (c     > row0 + 8) s0[nt][2] = -1e30f;
                if (c + 1 > row0 + 8) s0[nt][3] = -1e30f;
            }
        } else if (kt == 2 * qt + 1) {
            #pragma unroll
            for (int nt = 0; nt < 8; nt++) {
                s0[nt][0] = s0[nt][1] = s0[nt][2] = s0[nt][3] = -1e30f;
                int c = kt * 64 + nt * 8 + 2 * t;
                if (c     > row1)     s1[nt][0] = -1e30f;
                if (c + 1 > row1)     s1[nt][1] = -1e30f;
                if (c     > row1 + 8) s1[nt][2] = -1e30f;
                if (c + 1 > row1 + 8) s1[nt][3] = -1e30f;
            }
        }

        softmax_upd(s0, o0, m0a, m0b, l0a, l0b, pr0);
        softmax_upd(s1, o1, m1a, m1b, l1a, l1b, pr1);
        __syncwarp();

        CP_WAIT0();
        __syncthreads();
        if (kt + 1 < nkv) loadK(kt + 1);

        #pragma unroll
        for (int ks = 0; ks < 8; ks++) {
            int k0 = ks * 8;
            uint32_t af0[4], af1[4];
            af0[0] = __float_as_uint(QP[(size_t)pr0       * LDS_ + k0 + t]);
            af0[1] = __float_as_uint(QP[(size_t)(pr0 + 8) * LDS_ + k0 + t]);
            af0[2] = __float_as_uint(QP[(size_t)pr0       * LDS_ + k0 + t + 4]);
            af0[3] = __float_as_uint(QP[(size_t)(pr0 + 8) * LDS_ + k0 + t + 4]);
            af1[0] = __float_as_uint(QP[(size_t)pr1       * LDS_ + k0 + t]);
            af1[1] = __float_as_uint(QP[(size_t)(pr1 + 8) * LDS_ + k0 + t]);
            af1[2] = __float_as_uint(QP[(size_t)pr1       * LDS_ + k0 + t + 4]);
            af1[3] = __float_as_uint(QP[(size_t)(pr1 + 8) * LDS_ + k0 + t + 4]);
            #pragma unroll
            for (int nt = 0; nt < 8; nt++) {
                uint32_t bf[2];
                bf[0] = __float_as_uint(Vb[(k0 + t)     * LDS_ + nt * 8 + g]);
                bf[1] = __float_as_uint(Vb[(k0 + t + 4) * LDS_ + nt * 8 + g]);
                mma8(o0[nt], af0, bf);
                mma8(o1[nt], af1, bf);
            }
        }

        __syncthreads();
        if (kt + 1 < nkv) loadV(kt + 1);
    }

    float i0a = 1.f / l0a, i0b = 1.f / l0b;
    float i1a = 1.f / l1a, i1b = 1.f / l1b;
    float* O0 = g_att + ((size_t)b * T + row0) * E + h * 64;
    float* O1 = g_att + ((size_t)b * T + row1) * E + h * 64;
    #pragma unroll
    for (int nt = 0; nt < 8; nt++) {
        float2 w;
        w = {rtf(o0[nt][0] * i0a), rtf(o0[nt][1] * i0a)};
        *(float2*)&O0[nt * 8 + 2 * t] = w;
        w = {rtf(o0[nt][2] * i0b), rtf(o0[nt][3] * i0b)};
        *(float2*)&O0[8 * (size_t)E + nt * 8 + 2 * t] = w;
        w = {rtf(o1[nt][0] * i1a), rtf(o1[nt][1] * i1a)};
        *(float2*)&O1[nt * 8 + 2 * t] = w;
        w = {rtf(o1[nt][2] * i1b), rtf(o1[nt][3] * i1b)};
        *(float2*)&O1[8 * (size_t)E + nt * 8 + 2 * t] = w;
    }
}

// ---------------- launch ----------------
extern "C" void kernel_launch(void* const* d_in, const int* in_sizes, int n_in,
                              void* d_out, int out_size)
{
    const float* v    = (const float*)d_in[0];
    const float* k    = (const float*)d_in[1];
    const float* q    = (const float*)d_in[2];
    const float* ln_g = (const float*)d_in[3];
    const float* ln_b = (const float*)d_in[4];
    const float* Wq   = (const float*)d_in[5];
    const float* Wk   = (const float*)d_in[6];
    const float* Wv   = (const float*)d_in[7];
    const float* Wp   = (const float*)d_in[8];
    const float* bp   = (const float*)d_in[9];
    float* out = (float*)d_out;

    cudaFuncSetAttribute(gemm_qkv, cudaFuncAttributeMaxDynamicSharedMemorySize, GEMM_SMEM);
    cudaFuncSetAttribute(gemm_out, cudaFuncAttributeMaxDynamicSharedMemorySize, GEMM_SMEM);
    cudaFuncSetAttribute(attn_tc,  cudaFuncAttributeMaxDynamicSharedMemorySize, ATT_SMEM);

    // 0) pre-round weights + LayerNorm
    round_w<<<dim3(E * E / 1024, 4), 256>>>(Wq, Wk, Wv, Wp);
    ln_kernel<<<dim3(BT, 3), 256>>>(q, k, v, ln_g, ln_b);

    // 1) QKV projections, fused (z = stream); 128x256 tiles
    gemm_qkv<<<dim3(E / BN, BT / BM, 3), 256, GEMM_SMEM>>>();

    // 2) causal flash attention (128-row Q tiles, 2 m-tiles/warp)
    attn_tc<<<dim3(T / QROWS, H, B), 128, ATT_SMEM>>>();

    // 3) output projection + bias -> d_out
    gemm_out<<<dim3(E / BN, BT / BM), 256, GEMM_SMEM>>>(bp, out);
}

// round 9
// speedup vs baseline: 1.6601x; 1.4650x over previous
#include <cuda_runtime.h>
#include <cuda_fp16.h>
#include <math.h>
#include <stdint.h>

// Problem constants
constexpr int B  = 4;
constexpr int T  = 1024;
constexpr int E  = 1024;
constexpr int H  = 16;
constexpr int BT = B * T;              // 4096 rows
constexpr float EPS = 1e-5f;
constexpr float SCALE = 0.03125f;      // E^-0.5 = 1/32

// ---------------- scratch (no cudaMalloc allowed) ----------------
__device__ __half g_ln[3][BT * E];     // fp16 LN outputs [m][k]
__device__ __half g_wT[4][E * E];      // fp16 TRANSPOSED weights [n][k]
__device__ __half g_proj[3][BT * E];   // fp16 projected q/k/v [bt][h*64+d]
__device__ __half g_att[BT * E];       // fp16 attention out [bt][e]

// ---------------- helpers ----------------
__device__ __forceinline__ uint32_t h2u(__half2 h) { return *(uint32_t*)&h; }
__device__ __forceinline__ float ex2(float x) {
    float y; asm("ex2.approx.f32 %0, %1;" : "=f"(y) : "f"(x)); return y;
}
// fp16 mma m16n8k16, fp32 accum
__device__ __forceinline__ void mma16(float* c, const uint32_t* a, const uint32_t* b) {
    asm volatile(
        "mma.sync.aligned.m16n8k16.row.col.f32.f16.f16.f32 "
        "{%0,%1,%2,%3}, {%4,%5,%6,%7}, {%8,%9}, {%0,%1,%2,%3};"
        : "+f"(c[0]), "+f"(c[1]), "+f"(c[2]), "+f"(c[3])
        : "r"(a[0]), "r"(a[1]), "r"(a[2]), "r"(a[3]), "r"(b[0]), "r"(b[1]));
}
__device__ __forceinline__ void ldsm_x4_t(uint32_t& r0, uint32_t& r1,
                                          uint32_t& r2, uint32_t& r3, uint32_t addr) {
    asm volatile("ldmatrix.sync.aligned.m8n8.x4.trans.shared.b16 {%0,%1,%2,%3}, [%4];"
        : "=r"(r0), "=r"(r1), "=r"(r2), "=r"(r3) : "r"(addr));
}
__device__ __forceinline__ void cpasync16(void* s, const void* g) {
    uint32_t sa = (uint32_t)__cvta_generic_to_shared(s);
    asm volatile("cp.async.ca.shared.global [%0], [%1], 16;" :: "r"(sa), "l"(g));
}
#define CP_COMMIT() asm volatile("cp.async.commit_group;")
#define CP_WAIT0()  asm volatile("cp.async.wait_group 0;")
#define CP_WAIT1()  asm volatile("cp.async.wait_group 1;")

// ---------------- weight transpose + fp16 convert: g_wT[which][n][k] ----------------
__global__ void __launch_bounds__(256) round_wT(
    const float* __restrict__ wq, const float* __restrict__ wk,
    const float* __restrict__ wv, const float* __restrict__ wp)
{
    __shared__ float tile[32][33];
    int which = blockIdx.z;
    const float* src = (which == 0) ? wq : (which == 1) ? wk : (which == 2) ? wv : wp;
    __half* dst = g_wT[which];
    int k0 = blockIdx.y * 32, n0 = blockIdx.x * 32;
    int tx = threadIdx.x & 31, ty = threadIdx.x >> 5;
    #pragma unroll
    for (int i = 0; i < 4; i++)
        tile[ty + 8 * i][tx] = src[(size_t)(k0 + ty + 8 * i) * E + n0 + tx];
    __syncthreads();
    #pragma unroll
    for (int i = 0; i < 4; i++)
        dst[(size_t)(n0 + ty + 8 * i) * E + k0 + tx] = __float2half(tile[tx][ty + 8 * i]);
}

// ---------------- block reduction ----------------
__device__ __forceinline__ float block_sum_256(float v) {
    __shared__ float sh[8];
    int tid = threadIdx.x;
    #pragma unroll
    for (int o = 16; o; o >>= 1) v += __shfl_xor_sync(0xffffffffu, v, o);
    if ((tid & 31) == 0) sh[tid >> 5] = v;
    __syncthreads();
    float r = (tid < 8) ? sh[tid] : 0.f;
    if (tid < 32) {
        #pragma unroll
        for (int o = 4; o; o >>= 1) r += __shfl_xor_sync(0xffffffffu, r, o);
        if (tid == 0) sh[0] = r;
    }
    __syncthreads();
    r = sh[0];
    __syncthreads();
    return r;
}

// ---------------- LayerNorm -> fp16 ----------------
__global__ void __launch_bounds__(256) ln_kernel(
    const float* __restrict__ q, const float* __restrict__ k,
    const float* __restrict__ v, const float* __restrict__ gamma,
    const float* __restrict__ beta)
{
    int stream = blockIdx.y;
    int row    = blockIdx.x;
    const float* x = (stream == 0) ? q : (stream == 1) ? k : v;
    __half* y = g_ln[stream];
    x += (size_t)row * E;
    y += (size_t)row * E;
    int tid = threadIdx.x;

    float vals[4];
    float s = 0.f;
    #pragma unroll
    for (int i = 0; i < 4; i++) { vals[i] = x[tid + 256 * i]; s += vals[i]; }
    float mu = block_sum_256(s) * (1.f / E);

    float vs = 0.f;
    #pragma unroll
    for (int i = 0; i < 4; i++) { float d = vals[i] - mu; vs += d * d; }
    float var = block_sum_256(vs) * (1.f / E);
    float inv = rsqrtf(var + EPS);

    #pragma unroll
    for (int i = 0; i < 4; i++) {
        int e = tid + 256 * i;
        y[e] = __float2half((vals[i] - mu) * inv * gamma[e] + beta[e]);
    }
}

// ---------------- fp16 GEMM: CTA 128x256x32, warp 64x64 ----------------
constexpr int BM = 128, BN = 256, BK = 32;
constexpr int AS2 = 40;   // half stride (32 + 8 pad) -> conflict-free half2 frags
constexpr int BS2 = 40;
constexpr int ABUF = BM * AS2;       // halves
constexpr int BBUF = BN * BS2;
constexpr int GEMM_SMEM = (2 * ABUF + 2 * BBUF) * (int)sizeof(__half);  // 61440

template<bool OUT>
__device__ __forceinline__ void gemm_body(
    const __half* __restrict__ A, const __half* __restrict__ Wt,
    const float* __restrict__ bias, void* __restrict__ Cv)
{
    extern __shared__ __half smh[];
    __half* As = smh;               // [2][BM][AS2]
    __half* Bs = smh + 2 * ABUF;    // [2][BN][BS2]  (n-major, k contiguous)

    int m0 = blockIdx.y * BM, n0 = blockIdx.x * BN;
    int tid = threadIdx.x, lane = tid & 31, wid = tid >> 5;
    int g = lane >> 2, t = lane & 3;
    int wm = (wid & 1) * 64, wn = (wid >> 1) * 64;

    auto load_tiles = [&](int buf, int k0) {
        #pragma unroll
        for (int i = 0; i < 2; i++) {           // A: 128 rows x 4 chunks
            int idx = tid + i * 256; int r = idx >> 2, c8 = idx & 3;
            cpasync16(&As[buf * ABUF + r * AS2 + c8 * 8],
                      A + (size_t)(m0 + r) * E + k0 + c8 * 8);
        }
        #pragma unroll
        for (int i = 0; i < 4; i++) {           // B: 256 n-rows x 4 chunks
            int idx = tid + i * 256; int r = idx >> 2, c8 = idx & 3;
            cpasync16(&Bs[buf * BBUF + r * BS2 + c8 * 8],
                      Wt + (size_t)(n0 + r) * E + k0 + c8 * 8);
        }
        CP_COMMIT();
    };

    float acc[4][8][4] = {};
    load_tiles(0, 0);

    for (int kt = 0; kt < E / BK; kt++) {
        CP_WAIT0();
        __syncthreads();
        if (kt + 1 < E / BK) load_tiles((kt + 1) & 1, (kt + 1) * BK);
        const __half* a_ = &As[(kt & 1) * ABUF];
        const __half* b_ = &Bs[(kt & 1) * BBUF];
        #pragma unroll
        for (int ks = 0; ks < 2; ks++) {        // 2 x k16
            int k0 = ks * 16;
            uint32_t af[4][4], bf[8][2];
            #pragma unroll
            for (int mt = 0; mt < 4; mt++) {
                int mr = wm + mt * 16;
                af[mt][0] = *(const uint32_t*)&a_[(mr + g)     * AS2 + k0 + 2 * t];
                af[mt][1] = *(const uint32_t*)&a_[(mr + g + 8) * AS2 + k0 + 2 * t];
                af[mt][2] = *(const uint32_t*)&a_[(mr + g)     * AS2 + k0 + 2 * t + 8];
                af[mt][3] = *(const uint32_t*)&a_[(mr + g + 8) * AS2 + k0 + 2 * t + 8];
            }
            #pragma unroll
            for (int nt = 0; nt < 8; nt++) {
                int nr = wn + nt * 8 + g;
                bf[nt][0] = *(const uint32_t*)&b_[nr * BS2 + k0 + 2 * t];
                bf[nt][1] = *(const uint32_t*)&b_[nr * BS2 + k0 + 2 * t + 8];
            }
            #pragma unroll
            for (int mt = 0; mt < 4; mt++)
                #pragma unroll
                for (int nt = 0; nt < 8; nt++)
                    mma16(acc[mt][nt], af[mt], bf[nt]);
        }
    }

    #pragma unroll
    for (int mt = 0; mt < 4; mt++) {
        int r0 = m0 + wm + mt * 16 + g;
        #pragma unroll
        for (int nt = 0; nt < 8; nt++) {
            int c0 = n0 + wn + nt * 8 + 2 * t;
            if (OUT) {
                float* C = (float*)Cv;
                float b0 = bias[c0], b1 = bias[c0 + 1];
                float2 v;
                v.x = acc[mt][nt][0] + b0; v.y = acc[mt][nt][1] + b1;
                *(float2*)&C[(size_t)r0 * E + c0] = v;
                v.x = acc[mt][nt][2] + b0; v.y = acc[mt][nt][3] + b1;
                *(float2*)&C[(size_t)(r0 + 8) * E + c0] = v;
            } else {
                __half* C = (__half*)Cv;
                *(__half2*)&C[(size_t)r0 * E + c0] =
                    __floats2half2_rn(acc[mt][nt][0], acc[mt][nt][1]);
                *(__half2*)&C[(size_t)(r0 + 8) * E + c0] =
                    __floats2half2_rn(acc[mt][nt][2], acc[mt][nt][3]);
            }
        }
    }
}

__global__ void __launch_bounds__(256, 1) gemm_qkv() {
    int z = blockIdx.z;
    gemm_body<false>(g_ln[z], g_wT[z], nullptr, g_proj[z]);
}
__global__ void __launch_bounds__(256, 1) gemm_out(
    const float* __restrict__ bias, float* __restrict__ Cext) {
    gemm_body<true>(g_att, g_wT[3], bias, Cext);
}

// ---------------- fp16 flash attention: 128-row Q tile, 2 m-tiles/warp ----------------
constexpr int ST2 = 72;                 // half stride (64 + 8 pad)
constexpr int QROWS = 128;
constexpr int ATT_SMEM = (QROWS + 128) * ST2 * (int)sizeof(__half);  // 36864

__global__ void __launch_bounds__(128, 2) attn_tc() {
    extern __shared__ __half smh[];
    __half* QP = smh;                       // [128][72]: Q then P
    __half* Kb = smh + QROWS * ST2;         // [64][72]
    __half* Vb = Kb + 64 * ST2;             // [64][72]
    uint32_t vb_u32 = (uint32_t)__cvta_generic_to_shared(Vb);

    int qt = (gridDim.x - 1) - blockIdx.x;  // descending work order
    int h = blockIdx.y, b = blockIdx.z;
    const __half* Q = g_proj[0] + ((size_t)b * T + qt * QROWS) * E + h * 64;
    const __half* K = g_proj[1] + (size_t)b * T * E + h * 64;
    const __half* V = g_proj[2] + (size_t)b * T * E + h * 64;

    int tid = threadIdx.x, lane = tid & 31, wid = tid >> 5;
    int g = lane >> 2, t = lane & 3;

    auto loadK = [&](int kt) {
        const __half* Kg = K + (size_t)(kt * 64) * E;
        #pragma unroll
        for (int i = 0; i < 4; i++) {
            int idx = tid + i * 128; int r = idx >> 3, c8 = idx & 7;
            cpasync16(&Kb[r * ST2 + c8 * 8], Kg + (size_t)r * E + c8 * 8);
        }
        CP_COMMIT();
    };
    auto loadV = [&](int kt) {
        const __half* Vg = V + (size_t)(kt * 64) * E;
        #pragma unroll
        for (int i = 0; i < 4; i++) {
            int idx = tid + i * 128; int r = idx >> 3, c8 = idx & 7;
            cpasync16(&Vb[r * ST2 + c8 * 8], Vg + (size_t)r * E + c8 * 8);
        }
        CP_COMMIT();
    };

    // Q tile 128x64 halves (plain 16B loads), start K0/V0
    #pragma unroll
    for (int i = 0; i < 8; i++) {
        int idx = tid + i * 128; int r = idx >> 3, c8 = idx & 7;
        *(uint4*)&QP[r * ST2 + c8 * 8] = *(const uint4*)(Q + (size_t)r * E + c8 * 8);
    }
    loadK(0);
    loadV(0);
    __syncthreads();

    // Q fragments for both m-tiles, scaled by SCALE*log2e, repacked to half2
    const float QS = SCALE * 1.44269504f;
    uint32_t qf0[4][4], qf1[4][4];
    int mr0 = wid * 16, mr1 = 64 + wid * 16;
    #pragma unroll
    for (int ks = 0; ks < 4; ks++) {
        int k0 = ks * 16;
        #pragma unroll
        for (int j = 0; j < 4; j++) {
            int rr0 = (j & 1) ? 8 : 0;           // row offset (+8 for a1,a3)
            int cc  = (j & 2) ? 8 : 0;           // col offset (+8 for a2,a3)
            // NOTE: fragment order a0=(r,c) a1=(r+8,c) a2=(r,c+8) a3=(r+8,c+8)
            float2 f0 = __half22float2(*(const __half2*)&QP[(mr0 + g + rr0) * ST2 + k0 + 2 * t + cc]);
            float2 f1 = __half22float2(*(const __half2*)&QP[(mr1 + g + rr0) * ST2 + k0 + 2 * t + cc]);
            qf0[ks][j] = h2u(__floats2half2_rn(f0.x * QS, f0.y * QS));
            qf1[ks][j] = h2u(__floats2half2_rn(f1.x * QS, f1.y * QS));
        }
    }

    float o0[8][4] = {}, o1[8][4] = {};
    float m0a = -1e30f, m0b = -1e30f, l0a = 0.f, l0b = 0.f;
    float m1a = -1e30f, m1b = -1e30f, l1a = 0.f, l1b = 0.f;
    int pr0 = mr0 + g, pr1 = mr1 + g;
    int row0 = qt * QROWS + pr0, row1 = qt * QROWS + pr1;
    int nkv = 2 * qt + 2;

    auto softmax_upd = [&](float (&s)[8][4], float (&o)[8][4],
                           float& ma, float& mb, float& la, float& lb, int pr) {
        float mxa = -1e30f, mxb = -1e30f;
        #pragma unroll
        for (int nt = 0; nt < 8; nt++) {
            mxa = fmaxf(mxa, fmaxf(s[nt][0], s[nt][1]));
            mxb = fmaxf(mxb, fmaxf(s[nt][2], s[nt][3]));
        }
        mxa = fmaxf(mxa, __shfl_xor_sync(0xffffffffu, mxa, 1));
        mxa = fmaxf(mxa, __shfl_xor_sync(0xffffffffu, mxa, 2));
        mxb = fmaxf(mxb, __shfl_xor_sync(0xffffffffu, mxb, 1));
        mxb = fmaxf(mxb, __shfl_xor_sync(0xffffffffu, mxb, 2));
        float mna = fmaxf(ma, mxa), mnb = fmaxf(mb, mxb);
        float ca = ex2(ma - mna), cb = ex2(mb - mnb);
        float psa = 0.f, psb = 0.f;
        #pragma unroll
        for (int nt = 0; nt < 8; nt++) {
            float p0 = ex2(s[nt][0] - mna), p1 = ex2(s[nt][1] - mna);
            float p2 = ex2(s[nt][2] - mnb), p3 = ex2(s[nt][3] - mnb);
            psa += p0 + p1; psb += p2 + p3;
            *(__half2*)&QP[(size_t)pr * ST2 + nt * 8 + 2 * t] = __floats2half2_rn(p0, p1);
            *(__half2*)&QP[(size_t)(pr + 8) * ST2 + nt * 8 + 2 * t] = __floats2half2_rn(p2, p3);
        }
        psa += __shfl_xor_sync(0xffffffffu, psa, 1);
        psa += __shfl_xor_sync(0xffffffffu, psa, 2);
        psb += __shfl_xor_sync(0xffffffffu, psb, 1);
        psb += __shfl_xor_sync(0xffffffffu, psb, 2);
        la = la * ca + psa; lb = lb * cb + psb;
        ma = mna; mb = mnb;
        #pragma unroll
        for (int nt = 0; nt < 8; nt++) {
            o[nt][0] *= ca; o[nt][1] *= ca;
            o[nt][2] *= cb; o[nt][3] *= cb;
        }
    };

    for (int kt = 0; kt < nkv; kt++) {
        CP_WAIT1();          // K(kt) arrived
        __syncthreads();

        // S = Q @ K^T  (K fragment: K[key nt*8+g][d k0+2t..] half2)
        float s0[8][4] = {}, s1[8][4] = {};
        #pragma unroll
        for (int ks = 0; ks < 4; ks++) {
            int k0 = ks * 16;
            #pragma unroll
            for (int nt = 0; nt < 8; nt++) {
                uint32_t bf[2];
                bf[0] = *(const uint32_t*)&Kb[(nt * 8 + g) * ST2 + k0 + 2 * t];
                bf[1] = *(const uint32_t*)&Kb[(nt * 8 + g) * ST2 + k0 + 2 * t + 8];
                mma16(s0[nt], qf0[ks], bf);
                mma16(s1[nt], qf1[ks], bf);
            }
        }

        if (kt == 2 * qt) {
            #pragma unroll
            for (int nt = 0; nt < 8; nt++) {
                int c = kt * 64 + nt * 8 + 2 * t;
                if (c     > row0)     s0[nt][0] = -1e30f;
                if (c + 1 > row0)     s0[nt][1] = -1e30f;
                if (c     > row0 + 8) s0[nt][2] = -1e30f;
                if (c + 1 > row0 + 8) s0[nt][3] = -1e30f;
            }
        } else if (kt == 2 * qt + 1) {
            #pragma unroll
            for (int nt = 0; nt < 8; nt++) {
                s0[nt][0] = s0[nt][1] = s0[nt][2] = s0[nt][3] = -1e30f;
                int c = kt * 64 + nt * 8 + 2 * t;
                if (c     > row1)     s1[nt][0] = -1e30f;
                if (c + 1 > row1)     s1[nt][1] = -1e30f;
                if (c     > row1 + 8) s1[nt][2] = -1e30f;
                if (c + 1 > row1 + 8) s1[nt][3] = -1e30f;
            }
        }

        softmax_upd(s0, o0, m0a, m0b, l0a, l0b, pr0);
        softmax_upd(s1, o1, m1a, m1b, l1a, l1b, pr1);
        __syncwarp();

        CP_WAIT0();          // V(kt) arrived
        __syncthreads();     // + all warps done with K(kt)
        if (kt + 1 < nkv) loadK(kt + 1);   // overlaps PV

        // O += P @ V : P half2 loads, V via ldmatrix.x4.trans (2 ntiles/op)
        #pragma unroll
        for (int ks = 0; ks < 4; ks++) {
            int k0 = ks * 16;
            uint32_t af0[4], af1[4];
            af0[0] = *(const uint32_t*)&QP[(size_t)pr0       * ST2 + k0 + 2 * t];
            af0[1] = *(const uint32_t*)&QP[(size_t)(pr0 + 8) * ST2 + k0 + 2 * t];
            af0[2] = *(const uint32_t*)&QP[(size_t)pr0       * ST2 + k0 + 2 * t + 8];
            af0[3] = *(const uint32_t*)&QP[(size_t)(pr0 + 8) * ST2 + k0 + 2 * t + 8];
            af1[0] = *(const uint32_t*)&QP[(size_t)pr1       * ST2 + k0 + 2 * t];
            af1[1] = *(const uint32_t*)&QP[(size_t)(pr1 + 8) * ST2 + k0 + 2 * t];
            af1[2] = *(const uint32_t*)&QP[(size_t)pr1       * ST2 + k0 + 2 * t + 8];
            af1[3] = *(const uint32_t*)&QP[(size_t)(pr1 + 8) * ST2 + k0 + 2 * t + 8];
            #pragma unroll
            for (int ntp = 0; ntp < 4; ntp++) {     // ntile pairs
                uint32_t b0, b1, b2, b3;
                uint32_t addr = vb_u32 +
                    (((k0 + (lane & 15)) * ST2 + (ntp * 2 + (lane >> 4)) * 8) << 1);
                ldsm_x4_t(b0, b1, b2, b3, addr);
                uint32_t bfA[2] = {b0, b1}, bfB[2] = {b2, b3};
                mma16(o0[ntp * 2],     af0, bfA);
                mma16(o0[ntp * 2 + 1], af0, bfB);
                mma16(o1[ntp * 2],     af1, bfA);
                mma16(o1[ntp * 2 + 1], af1, bfB);
            }
        }

        __syncthreads();     // all warps done with V(kt)
        if (kt + 1 < nkv) loadV(kt + 1);   // overlaps next S
    }

    float i0a = 1.f / l0a, i0b = 1.f / l0b;
    float i1a = 1.f / l1a, i1b = 1.f / l1b;
    __half* O0 = g_att + ((size_t)b * T + row0) * E + h * 64;
    __half* O1 = g_att + ((size_t)b * T + row1) * E + h * 64;
    #pragma unroll
    for (int nt = 0; nt < 8; nt++) {
        *(__half2*)&O0[nt * 8 + 2 * t] =
            __floats2half2_rn(o0[nt][0] * i0a, o0[nt][1] * i0a);
        *(__half2*)&O0[8 * (size_t)E + nt * 8 + 2 * t] =
            __floats2half2_rn(o0[nt][2] * i0b, o0[nt][3] * i0b);
        *(__half2*)&O1[nt * 8 + 2 * t] =
            __floats2half2_rn(o1[nt][0] * i1a, o1[nt][1] * i1a);
        *(__half2*)&O1[8 * (size_t)E + nt * 8 + 2 * t] =
            __floats2half2_rn(o1[nt][2] * i1b, o1[nt][3] * i1b);
    }
}

// ---------------- launch ----------------
extern "C" void kernel_launch(void* const* d_in, const int* in_sizes, int n_in,
                              void* d_out, int out_size)
{
    const float* v    = (const float*)d_in[0];
    const float* k    = (const float*)d_in[1];
    const float* q    = (const float*)d_in[2];
    const float* ln_g = (const float*)d_in[3];
    const float* ln_b = (const float*)d_in[4];
    const float* Wq   = (const float*)d_in[5];
    const float* Wk   = (const float*)d_in[6];
    const float* Wv   = (const float*)d_in[7];
    const float* Wp   = (const float*)d_in[8];
    const float* bp   = (const float*)d_in[9];
    float* out = (float*)d_out;

    cudaFuncSetAttribute(gemm_qkv, cudaFuncAttributeMaxDynamicSharedMemorySize, GEMM_SMEM);
    cudaFuncSetAttribute(gemm_out, cudaFuncAttributeMaxDynamicSharedMemorySize, GEMM_SMEM);
    cudaFuncSetAttribute(attn_tc,  cudaFuncAttributeMaxDynamicSharedMemorySize, ATT_SMEM);

    // 0) weight transpose->fp16 + LayerNorm->fp16
    round_wT<<<dim3(E / 32, E / 32, 4), 256>>>(Wq, Wk, Wv, Wp);
    ln_kernel<<<dim3(BT, 3), 256>>>(q, k, v, ln_g, ln_b);

    // 1) QKV projections (fp16 tensor cores), fused
    gemm_qkv<<<dim3(E / BN, BT / BM, 3), 256, GEMM_SMEM>>>();

    // 2) causal flash attention (fp16 mma)
    attn_tc<<<dim3(T / QROWS, H, B), 128, ATT_SMEM>>>();

    // 3) output projection + bias -> d_out (fp32 accum + fp32 bias)
    gemm_out<<<dim3(E / BN, BT / BM), 256, GEMM_SMEM>>>(bp, out);
}

// round 10
// speedup vs baseline: 2.0564x; 1.2387x over previous
#include <cuda_runtime.h>
#include <cuda_fp16.h>
#include <math.h>
#include <stdint.h>

// Problem constants
constexpr int B  = 4;
constexpr int T  = 1024;
constexpr int E  = 1024;
constexpr int H  = 16;
constexpr int BT = B * T;              // 4096 rows
constexpr float EPS = 1e-5f;
constexpr float SCALE = 0.03125f;      // E^-0.5 = 1/32

// ---------------- scratch (no cudaMalloc allowed) ----------------
__device__ __half g_ln[3][BT * E];     // fp16 LN outputs [m][k]
__device__ __half g_wT[4][E * E];      // fp16 TRANSPOSED weights [n][k]
__device__ __half g_proj[3][BT * E];   // fp16 projected q/k/v [bt][h*64+d]
__device__ __half g_att[BT * E];       // fp16 attention out [bt][e]

// ---------------- helpers ----------------
__device__ __forceinline__ uint32_t h2u(__half2 h) { return *(uint32_t*)&h; }
__device__ __forceinline__ float ex2(float x) {
    float y; asm("ex2.approx.f32 %0, %1;" : "=f"(y) : "f"(x)); return y;
}
__device__ __forceinline__ void mma16(float* c, const uint32_t* a, const uint32_t* b) {
    asm volatile(
        "mma.sync.aligned.m16n8k16.row.col.f32.f16.f16.f32 "
        "{%0,%1,%2,%3}, {%4,%5,%6,%7}, {%8,%9}, {%0,%1,%2,%3};"
        : "+f"(c[0]), "+f"(c[1]), "+f"(c[2]), "+f"(c[3])
        : "r"(a[0]), "r"(a[1]), "r"(a[2]), "r"(a[3]), "r"(b[0]), "r"(b[1]));
}
__device__ __forceinline__ void ldsm_x4(uint32_t& r0, uint32_t& r1,
                                        uint32_t& r2, uint32_t& r3, uint32_t addr) {
    asm volatile("ldmatrix.sync.aligned.m8n8.x4.shared.b16 {%0,%1,%2,%3}, [%4];"
        : "=r"(r0), "=r"(r1), "=r"(r2), "=r"(r3) : "r"(addr));
}
__device__ __forceinline__ void ldsm_x4_t(uint32_t& r0, uint32_t& r1,
                                          uint32_t& r2, uint32_t& r3, uint32_t addr) {
    asm volatile("ldmatrix.sync.aligned.m8n8.x4.trans.shared.b16 {%0,%1,%2,%3}, [%4];"
        : "=r"(r0), "=r"(r1), "=r"(r2), "=r"(r3) : "r"(addr));
}
__device__ __forceinline__ void cpasync16(void* s, const void* g) {
    uint32_t sa = (uint32_t)__cvta_generic_to_shared(s);
    asm volatile("cp.async.ca.shared.global [%0], [%1], 16;" :: "r"(sa), "l"(g));
}
#define CP_COMMIT() asm volatile("cp.async.commit_group;")
#define CP_WAIT0()  asm volatile("cp.async.wait_group 0;")
#define CP_WAIT1()  asm volatile("cp.async.wait_group 1;")

// ---------------- weight transpose + fp16 convert ----------------
__global__ void __launch_bounds__(256) round_wT(
    const float* __restrict__ wq, const float* __restrict__ wk,
    const float* __restrict__ wv, const float* __restrict__ wp)
{
    __shared__ float tile[32][33];
    int which = blockIdx.z;
    const float* src = (which == 0) ? wq : (which == 1) ? wk : (which == 2) ? wv : wp;
    __half* dst = g_wT[which];
    int k0 = blockIdx.y * 32, n0 = blockIdx.x * 32;
    int tx = threadIdx.x & 31, ty = threadIdx.x >> 5;
    #pragma unroll
    for (int i = 0; i < 4; i++)
        tile[ty + 8 * i][tx] = src[(size_t)(k0 + ty + 8 * i) * E + n0 + tx];
    __syncthreads();
    #pragma unroll
    for (int i = 0; i < 4; i++)
        dst[(size_t)(n0 + ty + 8 * i) * E + k0 + tx] = __float2half(tile[tx][ty + 8 * i]);
}

// ---------------- block reduction ----------------
__device__ __forceinline__ float block_sum_256(float v) {
    __shared__ float sh[8];
    int tid = threadIdx.x;
    #pragma unroll
    for (int o = 16; o; o >>= 1) v += __shfl_xor_sync(0xffffffffu, v, o);
    if ((tid & 31) == 0) sh[tid >> 5] = v;
    __syncthreads();
    float r = (tid < 8) ? sh[tid] : 0.f;
    if (tid < 32) {
        #pragma unroll
        for (int o = 4; o; o >>= 1) r += __shfl_xor_sync(0xffffffffu, r, o);
        if (tid == 0) sh[0] = r;
    }
    __syncthreads();
    r = sh[0];
    __syncthreads();
    return r;
}

// ---------------- LayerNorm -> fp16 ----------------
__global__ void __launch_bounds__(256) ln_kernel(
    const float* __restrict__ q, const float* __restrict__ k,
    const float* __restrict__ v, const float* __restrict__ gamma,
    const float* __restrict__ beta)
{
    int stream = blockIdx.y;
    int row    = blockIdx.x;
    const float* x = (stream == 0) ? q : (stream == 1) ? k : v;
    __half* y = g_ln[stream];
    x += (size_t)row * E;
    y += (size_t)row * E;
    int tid = threadIdx.x;

    float vals[4];
    float s = 0.f;
    #pragma unroll
    for (int i = 0; i < 4; i++) { vals[i] = x[tid + 256 * i]; s += vals[i]; }
    float mu = block_sum_256(s) * (1.f / E);

    float vs = 0.f;
    #pragma unroll
    for (int i = 0; i < 4; i++) { float d = vals[i] - mu; vs += d * d; }
    float var = block_sum_256(vs) * (1.f / E);
    float inv = rsqrtf(var + EPS);

    #pragma unroll
    for (int i = 0; i < 4; i++) {
        int e = tid + 256 * i;
        y[e] = __float2half((vals[i] - mu) * inv * gamma[e] + beta[e]);
    }
}

// ---------------- fp16 GEMM: CTA 128x256x64, warp 64x64, ldmatrix frags ----------------
constexpr int BM = 128, BN = 256, BK = 64;
constexpr int AS2 = 72;              // halves (64 + 8 pad): conflict-free ldmatrix
constexpr int BS2 = 72;
constexpr int ABUF = BM * AS2;       // halves
constexpr int BBUF = BN * BS2;
constexpr int GEMM_SMEM = (2 * ABUF + 2 * BBUF) * (int)sizeof(__half);  // 110592

template<bool OUT>
__device__ __forceinline__ void gemm_body(
    const __half* __restrict__ A, const __half* __restrict__ Wt,
    const float* __restrict__ bias, void* __restrict__ Cv)
{
    extern __shared__ __half smh[];
    __half* As = smh;               // [2][BM][AS2]
    __half* Bs = smh + 2 * ABUF;    // [2][BN][BS2]  (n-major, k contiguous)
    uint32_t as_u = (uint32_t)__cvta_generic_to_shared(As);
    uint32_t bs_u = (uint32_t)__cvta_generic_to_shared(Bs);

    int m0 = blockIdx.y * BM, n0 = blockIdx.x * BN;
    int tid = threadIdx.x, lane = tid & 31, wid = tid >> 5;
    int g = lane >> 2, t = lane & 3;
    int wm = (wid & 1) * 64, wn = (wid >> 1) * 64;

    // ldmatrix lane address components
    int lm = lane >> 3;
    int arow = (lm & 1) * 8 + (lane & 7), acol = (lm >> 1) * 8;   // A: a0,a1=rows; a2,a3=+k8
    int brow = (lm >> 1) * 8 + (lane & 7), bcol = (lm & 1) * 8;   // B: m0,m1=k halves; m2,m3=+n8

    auto load_tiles = [&](int buf, int k0) {
        #pragma unroll
        for (int i = 0; i < 4; i++) {           // A: 128 rows x 8 chunks
            int idx = tid + i * 256; int r = idx >> 3, c8 = idx & 7;
            cpasync16(&As[buf * ABUF + r * AS2 + c8 * 8],
                      A + (size_t)(m0 + r) * E + k0 + c8 * 8);
        }
        #pragma unroll
        for (int i = 0; i < 8; i++) {           // B: 256 n-rows x 8 chunks
            int idx = tid + i * 256; int r = idx >> 3, c8 = idx & 7;
            cpasync16(&Bs[buf * BBUF + r * BS2 + c8 * 8],
                      Wt + (size_t)(n0 + r) * E + k0 + c8 * 8);
        }
        CP_COMMIT();
    };

    float acc[4][8][4] = {};
    load_tiles(0, 0);

    for (int kt = 0; kt < E / BK; kt++) {
        CP_WAIT0();
        __syncthreads();
        if (kt + 1 < E / BK) load_tiles((kt + 1) & 1, (kt + 1) * BK);
        uint32_t a_u = as_u + (kt & 1) * ABUF * 2;
        uint32_t b_u = bs_u + (kt & 1) * BBUF * 2;
        #pragma unroll
        for (int ks = 0; ks < 4; ks++) {        // 4 x k16
            int k0 = ks * 16;
            uint32_t af[4][4], bf[8][2];
            #pragma unroll
            for (int mt = 0; mt < 4; mt++)
                ldsm_x4(af[mt][0], af[mt][1], af[mt][2], af[mt][3],
                        a_u + (((wm + mt * 16 + arow) * AS2 + k0 + acol) << 1));
            #pragma unroll
            for (int i = 0; i < 4; i++)
                ldsm_x4(bf[2 * i][0], bf[2 * i][1], bf[2 * i + 1][0], bf[2 * i + 1][1],
                        b_u + (((wn + i * 16 + brow) * BS2 + k0 + bcol) << 1));
            #pragma unroll
            for (int mt = 0; mt < 4; mt++)
                #pragma unroll
                for (int nt = 0; nt < 8; nt++)
                    mma16(acc[mt][nt], af[mt], bf[nt]);
        }
    }

    #pragma unroll
    for (int mt = 0; mt < 4; mt++) {
        int r0 = m0 + wm + mt * 16 + g;
        #pragma unroll
        for (int nt = 0; nt < 8; nt++) {
            int c0 = n0 + wn + nt * 8 + 2 * t;
            if (OUT) {
                float* C = (float*)Cv;
                float b0 = bias[c0], b1 = bias[c0 + 1];
                float2 v;
                v.x = acc[mt][nt][0] + b0; v.y = acc[mt][nt][1] + b1;
                *(float2*)&C[(size_t)r0 * E + c0] = v;
                v.x = acc[mt][nt][2] + b0; v.y = acc[mt][nt][3] + b1;
                *(float2*)&C[(size_t)(r0 + 8) * E + c0] = v;
            } else {
                __half* C = (__half*)Cv;
                *(__half2*)&C[(size_t)r0 * E + c0] =
                    __floats2half2_rn(acc[mt][nt][0], acc[mt][nt][1]);
                *(__half2*)&C[(size_t)(r0 + 8) * E + c0] =
                    __floats2half2_rn(acc[mt][nt][2], acc[mt][nt][3]);
            }
        }
    }
}

__global__ void __launch_bounds__(256, 1) gemm_qkv() {
    int z = blockIdx.z;
    gemm_body<false>(g_ln[z], g_wT[z], nullptr, g_proj[z]);
}
__global__ void __launch_bounds__(256, 1) gemm_out(
    const float* __restrict__ bias, float* __restrict__ Cext) {
    gemm_body<true>(g_att, g_wT[3], bias, Cext);
}

// ---------------- fp16 flash attention: P in registers, ldmatrix K/V ----------------
constexpr int ST2 = 72;
constexpr int QROWS = 128;
constexpr int ATT_SMEM = (QROWS + 128) * ST2 * (int)sizeof(__half);  // 36864

__global__ void __launch_bounds__(128, 2) attn_tc() {
    extern __shared__ __half smh[];
    __half* Qs = smh;                       // [128][72]
    __half* Kb = smh + QROWS * ST2;         // [64][72]
    __half* Vb = Kb + 64 * ST2;             // [64][72]
    uint32_t kb_u32 = (uint32_t)__cvta_generic_to_shared(Kb);
    uint32_t vb_u32 = (uint32_t)__cvta_generic_to_shared(Vb);

    int qt = (gridDim.x - 1) - blockIdx.x;  // descending work order
    int h = blockIdx.y, b = blockIdx.z;
    const __half* Q = g_proj[0] + ((size_t)b * T + qt * QROWS) * E + h * 64;
    const __half* K = g_proj[1] + (size_t)b * T * E + h * 64;
    const __half* V = g_proj[2] + (size_t)b * T * E + h * 64;

    int tid = threadIdx.x, lane = tid & 31, wid = tid >> 5;
    int g = lane >> 2, t = lane & 3;
    int lm = lane >> 3;
    int krow = (lm >> 1) * 8 + (lane & 7), kcol = (lm & 1) * 8;  // K ldmatrix (B pattern)

    auto loadK = [&](int kt) {
        const __half* Kg = K + (size_t)(kt * 64) * E;
        #pragma unroll
        for (int i = 0; i < 4; i++) {
            int idx = tid + i * 128; int r = idx >> 3, c8 = idx & 7;
            cpasync16(&Kb[r * ST2 + c8 * 8], Kg + (size_t)r * E + c8 * 8);
        }
        CP_COMMIT();
    };
    auto loadV = [&](int kt) {
        const __half* Vg = V + (size_t)(kt * 64) * E;
        #pragma unroll
        for (int i = 0; i < 4; i++) {
            int idx = tid + i * 128; int r = idx >> 3, c8 = idx & 7;
            cpasync16(&Vb[r * ST2 + c8 * 8], Vg + (size_t)r * E + c8 * 8);
        }
        CP_COMMIT();
    };

    // Q tile 128x64 halves, start K0/V0
    #pragma unroll
    for (int i = 0; i < 8; i++) {
        int idx = tid + i * 128; int r = idx >> 3, c8 = idx & 7;
        *(uint4*)&Qs[r * ST2 + c8 * 8] = *(const uint4*)(Q + (size_t)r * E + c8 * 8);
    }
    loadK(0);
    loadV(0);
    __syncthreads();

    // Q fragments for both m-tiles, scaled by SCALE*log2e
    const float QS = SCALE * 1.44269504f;
    uint32_t qf0[4][4], qf1[4][4];
    int mr0 = wid * 16, mr1 = 64 + wid * 16;
    #pragma unroll
    for (int ks = 0; ks < 4; ks++) {
        int k0 = ks * 16;
        #pragma unroll
        for (int j = 0; j < 4; j++) {
            int rr0 = (j & 1) ? 8 : 0;
            int cc  = (j & 2) ? 8 : 0;
            float2 f0 = __half22float2(*(const __half2*)&Qs[(mr0 + g + rr0) * ST2 + k0 + 2 * t + cc]);
            float2 f1 = __half22float2(*(const __half2*)&Qs[(mr1 + g + rr0) * ST2 + k0 + 2 * t + cc]);
            qf0[ks][j] = h2u(__floats2half2_rn(f0.x * QS, f0.y * QS));
            qf1[ks][j] = h2u(__floats2half2_rn(f1.x * QS, f1.y * QS));
        }
    }

    float o0[8][4] = {}, o1[8][4] = {};
    float m0a = -1e30f, m0b = -1e30f, l0a = 0.f, l0b = 0.f;
    float m1a = -1e30f, m1b = -1e30f, l1a = 0.f, l1b = 0.f;
    int pr0 = mr0 + g, pr1 = mr1 + g;
    int row0 = qt * QROWS + pr0, row1 = qt * QROWS + pr1;
    int nkv = 2 * qt + 2;

    // softmax: p overwrites s, then packs into PV A-fragments (registers only)
    auto softmax_upd = [&](float (&s)[8][4], float (&o)[8][4], uint32_t (&af)[4][4],
                           float& ma, float& mb, float& la, float& lb) {
        float mxa = -1e30f, mxb = -1e30f;
        #pragma unroll
        for (int nt = 0; nt < 8; nt++) {
            mxa = fmaxf(mxa, fmaxf(s[nt][0], s[nt][1]));
            mxb = fmaxf(mxb, fmaxf(s[nt][2], s[nt][3]));
        }
        mxa = fmaxf(mxa, __shfl_xor_sync(0xffffffffu, mxa, 1));
        mxa = fmaxf(mxa, __shfl_xor_sync(0xffffffffu, mxa, 2));
        mxb = fmaxf(mxb, __shfl_xor_sync(0xffffffffu, mxb, 1));
        mxb = fmaxf(mxb, __shfl_xor_sync(0xffffffffu, mxb, 2));
        float mna = fmaxf(ma, mxa), mnb = fmaxf(mb, mxb);
        float ca = ex2(ma - mna), cb = ex2(mb - mnb);
        float psa = 0.f, psb = 0.f;
        #pragma unroll
        for (int nt = 0; nt < 8; nt++) {
            float p0 = ex2(s[nt][0] - mna), p1 = ex2(s[nt][1] - mna);
            float p2 = ex2(s[nt][2] - mnb), p3 = ex2(s[nt][3] - mnb);
            psa += p0 + p1; psb += p2 + p3;
            s[nt][0] = p0; s[nt][1] = p1; s[nt][2] = p2; s[nt][3] = p3;
        }
        psa += __shfl_xor_sync(0xffffffffu, psa, 1);
        psa += __shfl_xor_sync(0xffffffffu, psa, 2);
        psb += __shfl_xor_sync(0xffffffffu, psb, 1);
        psb += __shfl_xor_sync(0xffffffffu, psb, 2);
        la = la * ca + psa; lb = lb * cb + psb;
        ma = mna; mb = mnb;
        #pragma unroll
        for (int nt = 0; nt < 8; nt++) {
            o[nt][0] *= ca; o[nt][1] *= ca;
            o[nt][2] *= cb; o[nt][3] *= cb;
        }
        // repack: A-frag(k16 tile ks) = {row g k 2t.. , row g+8 k 2t.., row g k+8, row g+8 k+8}
        #pragma unroll
        for (int ks = 0; ks < 4; ks++) {
            af[ks][0] = h2u(__floats2half2_rn(s[2 * ks][0],     s[2 * ks][1]));
            af[ks][1] = h2u(__floats2half2_rn(s[2 * ks][2],     s[2 * ks][3]));
            af[ks][2] = h2u(__floats2half2_rn(s[2 * ks + 1][0], s[2 * ks + 1][1]));
            af[ks][3] = h2u(__floats2half2_rn(s[2 * ks + 1][2], s[2 * ks + 1][3]));
        }
    };

    for (int kt = 0; kt < nkv; kt++) {
        CP_WAIT1();          // K(kt) arrived
        __syncthreads();

        // S = Q @ K^T  (K fragments via ldmatrix.x4: 2 n-tiles per op)
        float s0[8][4] = {}, s1[8][4] = {};
        #pragma unroll
        for (int ks = 0; ks < 4; ks++) {
            int k0 = ks * 16;
            uint32_t bf[8][2];
            #pragma unroll
            for (int i = 0; i < 4; i++)
                ldsm_x4(bf[2 * i][0], bf[2 * i][1], bf[2 * i + 1][0], bf[2 * i + 1][1],
                        kb_u32 + (((i * 16 + krow) * ST2 + k0 + kcol) << 1));
            #pragma unroll
            for (int nt = 0; nt < 8; nt++) {
                mma16(s0[nt], qf0[ks], bf[nt]);
                mma16(s1[nt], qf1[ks], bf[nt]);
            }
        }

        if (kt == 2 * qt) {
            #pragma unroll
            for (int nt = 0; nt < 8; nt++) {
                int c = kt * 64 + nt * 8 + 2 * t;
                if (c     > row0)     s0[nt][0] = -1e30f;
                if (c + 1 > row0)     s0[nt][1] = -1e30f;
                if (c     > row0 + 8) s0[nt][2] = -1e30f;
                if (c + 1 > row0 + 8) s0[nt][3] = -1e30f;
            }
        } else if (kt == 2 * qt + 1) {
            #pragma unroll
            for (int nt = 0; nt < 8; nt++) {
                s0[nt][0] = s0[nt][1] = s0[nt][2] = s0[nt][3] = -1e30f;
                int c = kt * 64 + nt * 8 + 2 * t;
                if (c     > row1)     s1[nt][0] = -1e30f;
                if (c + 1 > row1)     s1[nt][1] = -1e30f;
                if (c     > row1 + 8) s1[nt][2] = -1e30f;
                if (c + 1 > row1 + 8) s1[nt][3] = -1e30f;
            }
        }

        uint32_t af0[4][4], af1[4][4];
        softmax_upd(s0, o0, af0, m0a, m0b, l0a, l0b);
        softmax_upd(s1, o1, af1, m1a, m1b, l1a, l1b);

        CP_WAIT0();          // V(kt) arrived
        __syncthreads();     // + all warps done with K(kt)
        if (kt + 1 < nkv) loadK(kt + 1);   // overlaps PV

        // O += P @ V : P fragments in regs, V via ldmatrix.x4.trans
        #pragma unroll
        for (int ks = 0; ks < 4; ks++) {
            int k0 = ks * 16;
            #pragma unroll
            for (int ntp = 0; ntp < 4; ntp++) {
                uint32_t b0, b1, b2, b3;
                uint32_t addr = vb_u32 +
                    (((k0 + (lane & 15)) * ST2 + (ntp * 2 + (lane >> 4)) * 8) << 1);
                ldsm_x4_t(b0, b1, b2, b3, addr);
                uint32_t bfA[2] = {b0, b1}, bfB[2] = {b2, b3};
                mma16(o0[ntp * 2],     af0[ks], bfA);
                mma16(o0[ntp * 2 + 1], af0[ks], bfB);
                mma16(o1[ntp * 2],     af1[ks], bfA);
                mma16(o1[ntp * 2 + 1], af1[ks], bfB);
            }
        }

        __syncthreads();     // all warps done with V(kt)
        if (kt + 1 < nkv) loadV(kt + 1);   // overlaps next S
    }

    float i0a = 1.f / l0a, i0b = 1.f / l0b;
    float i1a = 1.f / l1a, i1b = 1.f / l1b;
    __half* O0 = g_att + ((size_t)b * T + row0) * E + h * 64;
    __half* O1 = g_att + ((size_t)b * T + row1) * E + h * 64;
    #pragma unroll
    for (int nt = 0; nt < 8; nt++) {
        *(__half2*)&O0[nt * 8 + 2 * t] =
            __floats2half2_rn(o0[nt][0] * i0a, o0[nt][1] * i0a);
        *(__half2*)&O0[8 * (size_t)E + nt * 8 + 2 * t] =
            __floats2half2_rn(o0[nt][2] * i0b, o0[nt][3] * i0b);
        *(__half2*)&O1[nt * 8 + 2 * t] =
            __floats2half2_rn(o1[nt][0] * i1a, o1[nt][1] * i1a);
        *(__half2*)&O1[8 * (size_t)E + nt * 8 + 2 * t] =
            __floats2half2_rn(o1[nt][2] * i1b, o1[nt][3] * i1b);
    }
}

// ---------------- launch ----------------
extern "C" void kernel_launch(void* const* d_in, const int* in_sizes, int n_in,
                              void* d_out, int out_size)
{
    const float* v    = (const float*)d_in[0];
    const float* k    = (const float*)d_in[1];
    const float* q    = (const float*)d_in[2];
    const float* ln_g = (const float*)d_in[3];
    const float* ln_b = (const float*)d_in[4];
    const float* Wq   = (const float*)d_in[5];
    const float* Wk   = (const float*)d_in[6];
    const float* Wv   = (const float*)d_in[7];
    const float* Wp   = (const float*)d_in[8];
    const float* bp   = (const float*)d_in[9];
    float* out = (float*)d_out;

    cudaFuncSetAttribute(gemm_qkv, cudaFuncAttributeMaxDynamicSharedMemorySize, GEMM_SMEM);
    cudaFuncSetAttribute(gemm_out, cudaFuncAttributeMaxDynamicSharedMemorySize, GEMM_SMEM);
    cudaFuncSetAttribute(attn_tc,  cudaFuncAttributeMaxDynamicSharedMemorySize, ATT_SMEM);

    // 0) weight transpose->fp16 + LayerNorm->fp16
    round_wT<<<dim3(E / 32, E / 32, 4), 256>>>(Wq, Wk, Wv, Wp);
    ln_kernel<<<dim3(BT, 3), 256>>>(q, k, v, ln_g, ln_b);

    // 1) QKV projections (fp16 tensor cores, ldmatrix, BK=64), fused
    gemm_qkv<<<dim3(E / BN, BT / BM, 3), 256, GEMM_SMEM>>>();

    // 2) causal flash attention (fp16 mma, register P)
    attn_tc<<<dim3(T / QROWS, H, B), 128, ATT_SMEM>>>();

    // 3) output projection + bias -> d_out
    gemm_out<<<dim3(E / BN, BT / BM), 256, GEMM_SMEM>>>(bp, out);
}